// round 5
// baseline (speedup 1.0000x reference)
#include <cuda_runtime.h>
#include <cstdint>

#define LQ 512
#define LK 512
#define DD 256
#define HH1 256
#define HH2 128
#define BB 2

// global scratch: projections, [b][row][h] with h contiguous
__device__ float g_qp[BB * LQ * HH1];
__device__ float g_kp[BB * LK * HH1];

// ---------------------------------------------------------------------------
// Kernel 1: projections with smem-tiled W1.
// Block: 8 rows, 256 threads (thread = output h). W1 streamed in 64-d chunks.
// ---------------------------------------------------------------------------
#define PROJ_SMEM ((8 * 256 + 64 * 256) * 4)   // 72 KB

__global__ void __launch_bounds__(256, 2)
proj_kernel(const float* __restrict__ query,
            const float* __restrict__ key,
            const float* __restrict__ W1,
            const float* __restrict__ b1) {
    extern __shared__ float psm[];
    float* sx = psm;             // [8][256]
    float* sw = psm + 8 * 256;   // [64][256]

    const int h = threadIdx.x;
    const int r0 = blockIdx.x * 8;
    const int b = blockIdx.y;
    const int which = blockIdx.z;       // 0 -> query, 1 -> key

    {
        const float4* X4 = (const float4*)((which ? key : query) + ((long)b * LQ + r0) * DD);
        float4* sx4 = (float4*)sx;
        #pragma unroll
        for (int i = h; i < 512; i += 256) sx4[i] = __ldg(X4 + i);
    }

    float acc[8];
    const float bias = which ? 0.f : __ldg(b1 + h);
    #pragma unroll
    for (int r = 0; r < 8; r++) acc[r] = bias;

    #pragma unroll 1
    for (int dc = 0; dc < 4; dc++) {
        __syncthreads();
        {
            const float4* w4 = (const float4*)(W1 + (long)(which * DD + dc * 64) * HH1);
            float4* sw4 = (float4*)sw;
            #pragma unroll
            for (int i = h; i < 4096; i += 256) sw4[i] = __ldg(w4 + i);
        }
        __syncthreads();

        #pragma unroll
        for (int d4 = 0; d4 < 16; d4++) {
            const int d = dc * 64 + d4 * 4;
            const float w0 = sw[(d4 * 4 + 0) * 256 + h];
            const float w1 = sw[(d4 * 4 + 1) * 256 + h];
            const float w2 = sw[(d4 * 4 + 2) * 256 + h];
            const float w3 = sw[(d4 * 4 + 3) * 256 + h];
            #pragma unroll
            for (int r = 0; r < 8; r++) {
                float4 xv = *(const float4*)(sx + r * 256 + d);
                acc[r] = fmaf(xv.x, w0, acc[r]);
                acc[r] = fmaf(xv.y, w1, acc[r]);
                acc[r] = fmaf(xv.z, w2, acc[r]);
                acc[r] = fmaf(xv.w, w3, acc[r]);
            }
        }
    }

    float* dst = (which ? g_kp : g_qp) + ((long)b * LQ + r0) * HH1 + h;
    #pragma unroll
    for (int r = 0; r < 8; r++) dst[(long)r * HH1] = acc[r];
}

// ---------------------------------------------------------------------------
// Kernel 2: fused MLP scores via mma.sync tf32 (m16n8k8).
// CTA = 16 q x 16 k = 256 pairs (M), N = 128 (j), K = 256 (h).
// 512 threads / 16 warps (4 per SMSP): warp tile M=64 x N=32.
// A fragments built on the fly from qp/kp; acc = 64 regs/thread.
// ---------------------------------------------------------------------------
#define SQP 260        // qp/kp smem row stride (floats): bank-conflict free
#define SW2 136        // W2 smem row stride (floats):    bank-conflict free

#define OFF_W2   0                         // [256][136]
#define OFF_QP   (256 * SW2)               // [16][260]
#define OFF_KP   (OFF_QP + 16 * SQP)       // [16][260]
#define OFF_BW   (OFF_KP + 16 * SQP)       // float2[128] (b2, W3)
#define OFF_PART (OFF_BW + 256)            // float[4][256] cross-warp partials
#define SMEM_FLOATS (OFF_PART + 1024)
#define SMEM_BYTES (SMEM_FLOATS * 4)       // 177664

__device__ __forceinline__ void mma_tf32(float* c, const float* a, const float* b) {
    asm volatile(
        "mma.sync.aligned.m16n8k8.row.col.f32.tf32.tf32.f32 "
        "{%0,%1,%2,%3}, {%4,%5,%6,%7}, {%8,%9}, {%0,%1,%2,%3};"
        : "+f"(c[0]), "+f"(c[1]), "+f"(c[2]), "+f"(c[3])
        : "r"(__float_as_uint(a[0])), "r"(__float_as_uint(a[1])),
          "r"(__float_as_uint(a[2])), "r"(__float_as_uint(a[3])),
          "r"(__float_as_uint(b[0])), "r"(__float_as_uint(b[1])));
}

__global__ void __launch_bounds__(512, 1)
score_mma_kernel(const float* __restrict__ W2, const float* __restrict__ b2,
                 const float* __restrict__ W3, const float* __restrict__ b3,
                 float* __restrict__ scores) {
    extern __shared__ float smem[];
    const int tid = threadIdx.x;
    const int k0blk = blockIdx.x * 16, q0blk = blockIdx.y * 16, b = blockIdx.z;

    // ---- cooperative staging (512 threads) ----
    {
        const float4* src = (const float4*)W2;
        float4* dst = (float4*)(smem + OFF_W2);
        #pragma unroll 4
        for (int i4 = tid; i4 < 8192; i4 += 512) {
            int row = i4 >> 5, c4 = i4 & 31;
            dst[row * (SW2 / 4) + c4] = __ldg(src + i4);
        }
        const float4* gq = (const float4*)(g_qp + ((long)b * LQ + q0blk) * HH1);
        const float4* gk = (const float4*)(g_kp + ((long)b * LK + k0blk) * HH1);
        float4* dq = (float4*)(smem + OFF_QP);
        float4* dk = (float4*)(smem + OFF_KP);
        #pragma unroll
        for (int i4 = tid; i4 < 1024; i4 += 512) {
            int row = i4 >> 6, c4 = i4 & 63;
            dq[row * (SQP / 4) + c4] = __ldg(gq + i4);
            dk[row * (SQP / 4) + c4] = __ldg(gk + i4);
        }
        if (tid < HH2)
            ((float2*)(smem + OFF_BW))[tid] = make_float2(__ldg(b2 + tid), __ldg(W3 + tid));
    }
    __syncthreads();

    const int w = tid >> 5, lane = tid & 31;
    const int mwarp = w & 3;        // M offset = mwarp*64
    const int nwarp = w >> 2;       // N offset = nwarp*32
    const int n0 = nwarp * 32;
    const int lr = lane >> 2, lc = lane & 3;

    float acc[4][4][4];
    #pragma unroll
    for (int mt = 0; mt < 4; mt++)
        #pragma unroll
        for (int nt = 0; nt < 4; nt++)
            #pragma unroll
            for (int c = 0; c < 4; c++) acc[mt][nt][c] = 0.f;

    const float* kp0 = smem + OFF_KP + lr * SQP;          // k row = lr
    const float* kp1 = smem + OFF_KP + (lr + 8) * SQP;    // k row = lr+8
    const float* qpb = smem + OFF_QP + (mwarp * 4) * SQP; // q rows mwarp*4 + mt
    const float* w2b = smem + OFF_W2 + n0 + lr;           // + (k)*SW2 + 8*nt

    // fragment double buffers
    float kv[2][4], qv[2][4][2], bf[2][4][2];

#define LOAD_FRAG(B, K0) do { \
        kv[B][0] = kp0[(K0) + lc];     kv[B][1] = kp0[(K0) + lc + 4]; \
        kv[B][2] = kp1[(K0) + lc];     kv[B][3] = kp1[(K0) + lc + 4]; \
        _Pragma("unroll") \
        for (int mt = 0; mt < 4; mt++) { \
            qv[B][mt][0] = qpb[mt * SQP + (K0) + lc]; \
            qv[B][mt][1] = qpb[mt * SQP + (K0) + lc + 4]; \
        } \
        _Pragma("unroll") \
        for (int nt = 0; nt < 4; nt++) { \
            bf[B][nt][0] = w2b[((K0) + lc) * SW2 + 8 * nt]; \
            bf[B][nt][1] = w2b[((K0) + lc + 4) * SW2 + 8 * nt]; \
        } \
    } while (0)

    LOAD_FRAG(0, 0);

    #pragma unroll 2
    for (int k0 = 0; k0 < HH1; k0 += 8) {
        const int cur = (k0 >> 3) & 1;
        if (k0 + 8 < HH1) LOAD_FRAG(cur ^ 1, k0 + 8);

        float a[4][4];
        #pragma unroll
        for (int mt = 0; mt < 4; mt++) {
            a[mt][0] = fmaxf(qv[cur][mt][0] + kv[cur][0], 0.f);  // (lr,   lc)
            a[mt][1] = fmaxf(qv[cur][mt][0] + kv[cur][2], 0.f);  // (lr+8, lc)
            a[mt][2] = fmaxf(qv[cur][mt][1] + kv[cur][1], 0.f);  // (lr,   lc+4)
            a[mt][3] = fmaxf(qv[cur][mt][1] + kv[cur][3], 0.f);  // (lr+8, lc+4)
        }

        #pragma unroll
        for (int mt = 0; mt < 4; mt++)
            #pragma unroll
            for (int nt = 0; nt < 4; nt++)
                mma_tf32(acc[mt][nt], a[mt], bf[cur][nt]);
    }
#undef LOAD_FRAG

    // ---- epilogue: score(p) = b3 + sum_j relu(D[p][j]+b2[j])*W3[j] ----
    // D frag: c0:(lr, jj) c1:(lr, jj+1) c2:(lr+8, jj) c3:(lr+8, jj+1),
    // jj = n0 + nt*8 + 2*lc
    const float2* bw = (const float2*)(smem + OFF_BW);
    float* part = smem + OFF_PART;

    float s0[4], s1[4];
    #pragma unroll
    for (int mt = 0; mt < 4; mt++) {
        float t0 = 0.f, t1 = 0.f;
        #pragma unroll
        for (int nt = 0; nt < 4; nt++) {
            const int jj = n0 + nt * 8 + 2 * lc;
            float2 cA = bw[jj];
            float2 cB = bw[jj + 1];
            t0 = fmaf(fmaxf(acc[mt][nt][0] + cA.x, 0.f), cA.y, t0);
            t0 = fmaf(fmaxf(acc[mt][nt][1] + cB.x, 0.f), cB.y, t0);
            t1 = fmaf(fmaxf(acc[mt][nt][2] + cA.x, 0.f), cA.y, t1);
            t1 = fmaf(fmaxf(acc[mt][nt][3] + cB.x, 0.f), cB.y, t1);
        }
        s0[mt] = t0; s1[mt] = t1;
    }
    #pragma unroll
    for (int off = 1; off < 4; off <<= 1)
        #pragma unroll
        for (int mt = 0; mt < 4; mt++) {
            s0[mt] += __shfl_xor_sync(0xffffffffu, s0[mt], off);
            s1[mt] += __shfl_xor_sync(0xffffffffu, s1[mt], off);
        }

    if (lc == 0) {
        #pragma unroll
        for (int mt = 0; mt < 4; mt++) {
            part[nwarp * 256 + mwarp * 64 + mt * 16 + lr]     = s0[mt];
            part[nwarp * 256 + mwarp * 64 + mt * 16 + lr + 8] = s1[mt];
        }
    }
    __syncthreads();
    if (tid < 256) {
        const float bb3 = __ldg(b3);
        const int p = tid;
        float f = part[p] + part[256 + p] + part[512 + p] + part[768 + p] + bb3;
        const int q = q0blk + (p >> 4);
        scores[((long)b * LQ + q) * LK + k0blk + (p & 15)] = f;
    }
}

// ---------------------------------------------------------------------------
// Kernel 3: mask + softmax over k (warp-per-row, 8 rows/block) + out = attn@V.
// ---------------------------------------------------------------------------
__global__ void __launch_bounds__(256, 1)
softmax_av_kernel(const float* __restrict__ value,
                  const int* __restrict__ mask,
                  float* __restrict__ out,
                  float* __restrict__ attn) {
    __shared__ float srow[8][LK];
    const int b = blockIdx.y;
    const int q0 = blockIdx.x * 8;
    const int tid = threadIdx.x;
    const int w = tid >> 5, lane = tid & 31;

    {
        const int r = w;
        const long rowbase = ((long)b * LQ + q0 + r) * LK;
        float vals[16];
        float mx = -3.4e38f;
        #pragma unroll
        for (int i = 0; i < 16; i++) {
            int k = lane + i * 32;
            float s = attn[rowbase + k];
            if (mask[rowbase + k] == 0) s = -1e9f;
            vals[i] = s;
            mx = fmaxf(mx, s);
        }
        #pragma unroll
        for (int off = 16; off > 0; off >>= 1)
            mx = fmaxf(mx, __shfl_xor_sync(0xffffffffu, mx, off));

        float sum = 0.f;
        #pragma unroll
        for (int i = 0; i < 16; i++) {
            vals[i] = __expf(vals[i] - mx);
            sum += vals[i];
        }
        #pragma unroll
        for (int off = 16; off > 0; off >>= 1)
            sum += __shfl_xor_sync(0xffffffffu, sum, off);
        const float inv = 1.f / sum;

        #pragma unroll
        for (int i = 0; i < 16; i++) {
            int k = lane + i * 32;
            float a = vals[i] * inv;
            srow[r][k] = a;
            attn[rowbase + k] = a;
        }
    }
    __syncthreads();

    // out = attn @ V   (thread = one output dim d, 8 rows accumulated)
    const int d = tid;
    float acc[8] = {0.f, 0.f, 0.f, 0.f, 0.f, 0.f, 0.f, 0.f};
    const float* Vb = value + (long)b * LK * DD + d;
    #pragma unroll 4
    for (int k = 0; k < LK; k++) {
        float v = __ldg(Vb + (long)k * DD);
        #pragma unroll
        for (int r = 0; r < 8; r++) acc[r] = fmaf(srow[r][k], v, acc[r]);
    }
    #pragma unroll
    for (int r = 0; r < 8; r++)
        out[((long)b * LQ + q0 + r) * DD + d] = acc[r];
}

// ---------------------------------------------------------------------------
extern "C" void kernel_launch(void* const* d_in, const int* in_sizes, int n_in,
                              void* d_out, int out_size) {
    const float* query = (const float*)d_in[0];
    const float* key   = (const float*)d_in[1];
    const float* value = (const float*)d_in[2];
    const int*   mask  = (const int*)d_in[3];
    const float* W1 = (const float*)d_in[4];
    const float* b1 = (const float*)d_in[5];
    const float* W2 = (const float*)d_in[6];
    const float* b2 = (const float*)d_in[7];
    const float* W3 = (const float*)d_in[8];
    const float* b3 = (const float*)d_in[9];

    float* out  = (float*)d_out;                 // [B, LQ, D]
    float* attn = out + (long)BB * LQ * DD;      // [B, LQ, LK]

    cudaFuncSetAttribute(proj_kernel,
                         cudaFuncAttributeMaxDynamicSharedMemorySize, PROJ_SMEM);
    cudaFuncSetAttribute(score_mma_kernel,
                         cudaFuncAttributeMaxDynamicSharedMemorySize, SMEM_BYTES);

    proj_kernel<<<dim3(LQ / 8, BB, 2), 256, PROJ_SMEM>>>(query, key, W1, b1);
    score_mma_kernel<<<dim3(LK / 16, LQ / 16, BB), 512, SMEM_BYTES>>>(W2, b2, W3, b3, attn);
    softmax_av_kernel<<<dim3(LQ / 8, BB), 256>>>(value, mask, out, attn);
}

// round 6
// speedup vs baseline: 1.4651x; 1.4651x over previous
#include <cuda_runtime.h>
#include <cuda_bf16.h>
#include <cstdint>

#define LQ 512
#define LK 512
#define DD 256
#define HH1 256
#define HH2 128
#define BB 2

// global scratch: projections [b][row][h_perm] (h contiguous, permuted within 16)
__device__ float g_qp[BB * LQ * HH1];
__device__ float g_kp[BB * LK * HH1];
// W2^T, bf16, [j=128][h_perm stride 272]
__device__ uint4 g_w2bt4[4352];

// perm within 16-block: orig o -> pos ((o&6)<<1) + (o&1) + ((o&8)>>2)
__device__ __forceinline__ int hperm(int h) {
    int o = h & 15;
    return (h & ~15) + ((o & 6) << 1) + (o & 1) + ((o & 8) >> 2);
}

// ---------------------------------------------------------------------------
// Kernel 0: W2 [h][j] -> g_w2bt4 bf16 [j][perm(h)], row stride 272
// ---------------------------------------------------------------------------
__global__ void w2bt_kernel(const float* __restrict__ W2) {
    int idx = blockIdx.x * 256 + threadIdx.x;   // 32768 = 256h * 128j
    int j = idx & 127, h = idx >> 7;
    float v = __ldg(W2 + h * HH2 + j);
    __nv_bfloat16 bv = __float2bfloat16(v);
    ((uint16_t*)g_w2bt4)[j * 272 + hperm(h)] = *(uint16_t*)&bv;
}

// ---------------------------------------------------------------------------
// Kernel 1: projections with smem-tiled W1 (R4 config) + permuted h write.
// ---------------------------------------------------------------------------
#define PROJ_SMEM ((16 * 256 + 64 * 256) * 4)   // 80 KB

__global__ void __launch_bounds__(256, 1)
proj_kernel(const float* __restrict__ query,
            const float* __restrict__ key,
            const float* __restrict__ W1,
            const float* __restrict__ b1) {
    extern __shared__ float psm[];
    float* sx = psm;              // [16][256]
    float* sw = psm + 16 * 256;   // [64][256]

    const int h = threadIdx.x;
    const int r0 = blockIdx.x * 16;
    const int b = blockIdx.y;
    const int which = blockIdx.z;       // 0 -> query, 1 -> key

    {
        const float4* X4 = (const float4*)((which ? key : query) + ((long)b * LQ + r0) * DD);
        float4* sx4 = (float4*)sx;
        #pragma unroll
        for (int i = h; i < 1024; i += 256) sx4[i] = __ldg(X4 + i);
    }

    float acc[16];
    const float bias = which ? 0.f : __ldg(b1 + h);
    #pragma unroll
    for (int r = 0; r < 16; r++) acc[r] = bias;

    #pragma unroll 1
    for (int dc = 0; dc < 4; dc++) {
        __syncthreads();
        {
            const float4* w4 = (const float4*)(W1 + (long)(which * DD + dc * 64) * HH1);
            float4* sw4 = (float4*)sw;
            #pragma unroll
            for (int i = h; i < 4096; i += 256) sw4[i] = __ldg(w4 + i);
        }
        __syncthreads();

        #pragma unroll
        for (int d4 = 0; d4 < 16; d4++) {
            const int d = dc * 64 + d4 * 4;
            const float w0 = sw[(d4 * 4 + 0) * 256 + h];
            const float w1 = sw[(d4 * 4 + 1) * 256 + h];
            const float w2 = sw[(d4 * 4 + 2) * 256 + h];
            const float w3 = sw[(d4 * 4 + 3) * 256 + h];
            #pragma unroll
            for (int r = 0; r < 16; r++) {
                float4 xv = *(const float4*)(sx + r * 256 + d);
                acc[r] = fmaf(xv.x, w0, acc[r]);
                acc[r] = fmaf(xv.y, w1, acc[r]);
                acc[r] = fmaf(xv.z, w2, acc[r]);
                acc[r] = fmaf(xv.w, w3, acc[r]);
            }
        }
    }

    float* dst = (which ? g_kp : g_qp) + ((long)b * LQ + r0) * HH1 + hperm(h);
    #pragma unroll
    for (int r = 0; r < 16; r++) dst[(long)r * HH1] = acc[r];
}

// ---------------------------------------------------------------------------
// Kernel 2: fused MLP scores via mma.sync m16n8k16 bf16.
// CTA = 256 pairs (M) x 128 j (N), K = 256 (h).  512 threads / 16 warps.
// Warp tile M=64 x N=32 (4 mt x 4 nt).  A built on the fly (permuted loads).
// ---------------------------------------------------------------------------
#define OFF_W2B   0                    // bytes: bf16 [128][272] = 69632
#define OFF_QPB   69632                // fp32 [16][272] = 17408
#define OFF_KPB   87040                // fp32 [16][272]
#define OFF_BWB   104448               // float2[128]
#define OFF_PARTB 105472               // float[4*256]
#define SMEM_BYTES 109568

__device__ __forceinline__ uint32_t pack_relu_bf16(float lo, float hi) {
    uint32_t r;
    asm("cvt.rn.bf16x2.f32 %0, %1, %2;" : "=r"(r) : "f"(hi), "f"(lo));
    asm("max.bf16x2 %0, %0, %1;" : "+r"(r) : "r"(0u));
    return r;
}

__device__ __forceinline__ void mma_bf16(float* c, const uint32_t* a, const uint32_t* b) {
    asm volatile(
        "mma.sync.aligned.m16n8k16.row.col.f32.bf16.bf16.f32 "
        "{%0,%1,%2,%3}, {%4,%5,%6,%7}, {%8,%9}, {%0,%1,%2,%3};"
        : "+f"(c[0]), "+f"(c[1]), "+f"(c[2]), "+f"(c[3])
        : "r"(a[0]), "r"(a[1]), "r"(a[2]), "r"(a[3]), "r"(b[0]), "r"(b[1]));
}

__global__ void __launch_bounds__(512, 1)
score_mma_kernel(const float* __restrict__ b2, const float* __restrict__ W3,
                 const float* __restrict__ b3, float* __restrict__ scores) {
    extern __shared__ char smem[];
    float* smemf = (float*)smem;
    const int tid = threadIdx.x;
    const int k0blk = blockIdx.x * 16, q0blk = blockIdx.y * 16, b = blockIdx.z;

    // ---- cooperative staging ----
    {
        uint4* dW = (uint4*)(smem + OFF_W2B);
        #pragma unroll 4
        for (int i = tid; i < 4352; i += 512) dW[i] = g_w2bt4[i];

        const float4* gq = (const float4*)(g_qp + ((long)b * LQ + q0blk) * HH1);
        const float4* gk = (const float4*)(g_kp + ((long)b * LK + k0blk) * HH1);
        float4* dq = (float4*)(smem + OFF_QPB);
        float4* dk = (float4*)(smem + OFF_KPB);
        #pragma unroll
        for (int i4 = tid; i4 < 1024; i4 += 512) {
            int r = i4 >> 6, c = i4 & 63;
            dq[r * 68 + c] = __ldg(gq + i4);
            dk[r * 68 + c] = __ldg(gk + i4);
        }
        if (tid < HH2)
            ((float2*)(smem + OFF_BWB))[tid] = make_float2(__ldg(b2 + tid), __ldg(W3 + tid));
    }
    __syncthreads();

    const int w = tid >> 5, lane = tid & 31;
    const int mwarp = w & 3;        // M offset = mwarp*64
    const int nwarp = w >> 2;       // N offset = nwarp*32
    const int n0 = nwarp * 32;
    const int lr = lane >> 2, lc = lane & 3;

    float acc[4][4][4];
    #pragma unroll
    for (int mt = 0; mt < 4; mt++)
        #pragma unroll
        for (int nt = 0; nt < 4; nt++)
            #pragma unroll
            for (int c = 0; c < 4; c++) acc[mt][nt][c] = 0.f;

    const float* kpA = smemf + OFF_KPB / 4 + lr * 272 + 4 * lc;
    const float* kpB = kpA + 8 * 272;
    const float* qpb = smemf + OFF_QPB / 4 + (mwarp * 4) * 272 + 4 * lc;
    const uint16_t* w2p = (const uint16_t*)(smem + OFF_W2B) + (n0 + lr) * 272 + 4 * lc;

    #pragma unroll 4
    for (int c = 0; c < 16; c++) {
        const int hb = c * 16;
        const float4 kA = *(const float4*)(kpA + hb);
        const float4 kB = *(const float4*)(kpB + hb);
        uint2 bfr[4];
        #pragma unroll
        for (int nt = 0; nt < 4; nt++)
            bfr[nt] = *(const uint2*)(w2p + nt * (8 * 272) + hb);

        #pragma unroll
        for (int mt = 0; mt < 4; mt++) {
            const float4 q4 = *(const float4*)(qpb + mt * 272 + hb);
            uint32_t a[4];
            a[0] = pack_relu_bf16(q4.x + kA.x, q4.y + kA.y);   // row lr,   k 2lc,2lc+1
            a[1] = pack_relu_bf16(q4.x + kB.x, q4.y + kB.y);   // row lr+8, k 2lc,2lc+1
            a[2] = pack_relu_bf16(q4.z + kA.z, q4.w + kA.w);   // row lr,   k 2lc+8,9
            a[3] = pack_relu_bf16(q4.z + kB.z, q4.w + kB.w);   // row lr+8, k 2lc+8,9
            #pragma unroll
            for (int nt = 0; nt < 4; nt++)
                mma_bf16(acc[mt][nt], a, (const uint32_t*)&bfr[nt]);
        }
    }

    // ---- epilogue: score(p) = b3 + sum_j relu(D[p][j]+b2[j])*W3[j] ----
    // D frag: c0:(lr, jj) c1:(lr, jj+1) c2:(lr+8, jj) c3:(lr+8, jj+1),
    // jj = n0 + nt*8 + 2*lc
    const float2* bw = (const float2*)(smem + OFF_BWB);
    float* part = smemf + OFF_PARTB / 4;

    float s0[4], s1[4];
    #pragma unroll
    for (int mt = 0; mt < 4; mt++) {
        float t0 = 0.f, t1 = 0.f;
        #pragma unroll
        for (int nt = 0; nt < 4; nt++) {
            const int jj = n0 + nt * 8 + 2 * lc;
            float2 cA = bw[jj];
            float2 cB = bw[jj + 1];
            t0 = fmaf(fmaxf(acc[mt][nt][0] + cA.x, 0.f), cA.y, t0);
            t0 = fmaf(fmaxf(acc[mt][nt][1] + cB.x, 0.f), cB.y, t0);
            t1 = fmaf(fmaxf(acc[mt][nt][2] + cA.x, 0.f), cA.y, t1);
            t1 = fmaf(fmaxf(acc[mt][nt][3] + cB.x, 0.f), cB.y, t1);
        }
        s0[mt] = t0; s1[mt] = t1;
    }
    #pragma unroll
    for (int off = 1; off < 4; off <<= 1)
        #pragma unroll
        for (int mt = 0; mt < 4; mt++) {
            s0[mt] += __shfl_xor_sync(0xffffffffu, s0[mt], off);
            s1[mt] += __shfl_xor_sync(0xffffffffu, s1[mt], off);
        }

    if (lc == 0) {
        #pragma unroll
        for (int mt = 0; mt < 4; mt++) {
            part[nwarp * 256 + mwarp * 64 + mt * 16 + lr]     = s0[mt];
            part[nwarp * 256 + mwarp * 64 + mt * 16 + lr + 8] = s1[mt];
        }
    }
    __syncthreads();
    if (tid < 256) {
        const float bb3 = __ldg(b3);
        const int p = tid;
        float f = part[p] + part[256 + p] + part[512 + p] + part[768 + p] + bb3;
        const int q = q0blk + (p >> 4);
        scores[((long)b * LQ + q) * LK + k0blk + (p & 15)] = f;
    }
}

// ---------------------------------------------------------------------------
// Kernel 3: mask + softmax over k (warp-per-row, 8 rows/block) + out = attn@V.
// ---------------------------------------------------------------------------
__global__ void __launch_bounds__(256, 1)
softmax_av_kernel(const float* __restrict__ value,
                  const int* __restrict__ mask,
                  float* __restrict__ out,
                  float* __restrict__ attn) {
    __shared__ float srow[8][LK];
    const int b = blockIdx.y;
    const int q0 = blockIdx.x * 8;
    const int tid = threadIdx.x;
    const int w = tid >> 5, lane = tid & 31;

    {
        const int r = w;
        const long rowbase = ((long)b * LQ + q0 + r) * LK;
        float vals[16];
        float mx = -3.4e38f;
        #pragma unroll
        for (int i = 0; i < 16; i++) {
            int k = lane + i * 32;
            float s = attn[rowbase + k];
            if (mask[rowbase + k] == 0) s = -1e9f;
            vals[i] = s;
            mx = fmaxf(mx, s);
        }
        #pragma unroll
        for (int off = 16; off > 0; off >>= 1)
            mx = fmaxf(mx, __shfl_xor_sync(0xffffffffu, mx, off));

        float sum = 0.f;
        #pragma unroll
        for (int i = 0; i < 16; i++) {
            vals[i] = __expf(vals[i] - mx);
            sum += vals[i];
        }
        #pragma unroll
        for (int off = 16; off > 0; off >>= 1)
            sum += __shfl_xor_sync(0xffffffffu, sum, off);
        const float inv = 1.f / sum;

        #pragma unroll
        for (int i = 0; i < 16; i++) {
            int k = lane + i * 32;
            float a = vals[i] * inv;
            srow[r][k] = a;
            attn[rowbase + k] = a;
        }
    }
    __syncthreads();

    // out = attn @ V   (thread = one output dim d, 8 rows accumulated)
    const int d = tid;
    float acc[8] = {0.f, 0.f, 0.f, 0.f, 0.f, 0.f, 0.f, 0.f};
    const float* Vb = value + (long)b * LK * DD + d;
    #pragma unroll 4
    for (int k = 0; k < LK; k++) {
        float v = __ldg(Vb + (long)k * DD);
        #pragma unroll
        for (int r = 0; r < 8; r++) acc[r] = fmaf(srow[r][k], v, acc[r]);
    }
    #pragma unroll
    for (int r = 0; r < 8; r++)
        out[((long)b * LQ + q0 + r) * DD + d] = acc[r];
}

// ---------------------------------------------------------------------------
extern "C" void kernel_launch(void* const* d_in, const int* in_sizes, int n_in,
                              void* d_out, int out_size) {
    const float* query = (const float*)d_in[0];
    const float* key   = (const float*)d_in[1];
    const float* value = (const float*)d_in[2];
    const int*   mask  = (const int*)d_in[3];
    const float* W1 = (const float*)d_in[4];
    const float* b1 = (const float*)d_in[5];
    const float* W2 = (const float*)d_in[6];
    const float* b2 = (const float*)d_in[7];
    const float* W3 = (const float*)d_in[8];
    const float* b3 = (const float*)d_in[9];

    float* out  = (float*)d_out;                 // [B, LQ, D]
    float* attn = out + (long)BB * LQ * DD;      // [B, LQ, LK]

    cudaFuncSetAttribute(proj_kernel,
                         cudaFuncAttributeMaxDynamicSharedMemorySize, PROJ_SMEM);
    cudaFuncSetAttribute(score_mma_kernel,
                         cudaFuncAttributeMaxDynamicSharedMemorySize, SMEM_BYTES);

    w2bt_kernel<<<128, 256>>>(W2);
    proj_kernel<<<dim3(LQ / 16, BB, 2), 256, PROJ_SMEM>>>(query, key, W1, b1);
    score_mma_kernel<<<dim3(LK / 16, LQ / 16, BB), 512, SMEM_BYTES>>>(b2, W3, b3, attn);
    softmax_av_kernel<<<dim3(LQ / 8, BB), 256>>>(value, mask, out, attn);
}

// round 7
// speedup vs baseline: 1.6456x; 1.1232x over previous
#include <cuda_runtime.h>
#include <cuda_bf16.h>
#include <cstdint>

#define LQ 512
#define LK 512
#define DD 256
#define HH1 256
#define HH2 128
#define BB 2
#define KSPLIT 4

// global scratch: projections [b][row][h_perm] (h contiguous, permuted within 16)
__device__ float g_qp[BB * LQ * HH1];
__device__ float g_kp[BB * LK * HH1];
// W2^T, bf16, [j=128][h_perm stride 272]
__device__ uint4 g_w2bt4[4352];
// AV partial sums [ks][b][q][d]
__device__ float g_av[KSPLIT * BB * LQ * DD];

// perm within 16-block: orig o -> pos ((o&6)<<1) + (o&1) + ((o&8)>>2)
__device__ __forceinline__ int hperm(int h) {
    int o = h & 15;
    return (h & ~15) + ((o & 6) << 1) + (o & 1) + ((o & 8) >> 2);
}

// ---------------------------------------------------------------------------
// Kernel 0: W2 [h][j] -> g_w2bt4 bf16 [j][perm(h)], row stride 272
// ---------------------------------------------------------------------------
__global__ void w2bt_kernel(const float* __restrict__ W2) {
    int idx = blockIdx.x * 256 + threadIdx.x;   // 32768 = 256h * 128j
    int j = idx & 127, h = idx >> 7;
    float v = __ldg(W2 + h * HH2 + j);
    __nv_bfloat16 bv = __float2bfloat16(v);
    ((uint16_t*)g_w2bt4)[j * 272 + hperm(h)] = *(uint16_t*)&bv;
}

// ---------------------------------------------------------------------------
// Kernel 1: projections with smem-tiled W1 + permuted h write.
// ---------------------------------------------------------------------------
#define PROJ_SMEM ((16 * 256 + 64 * 256) * 4)   // 80 KB

__global__ void __launch_bounds__(256, 1)
proj_kernel(const float* __restrict__ query,
            const float* __restrict__ key,
            const float* __restrict__ W1,
            const float* __restrict__ b1) {
    extern __shared__ float psm[];
    float* sx = psm;              // [16][256]
    float* sw = psm + 16 * 256;   // [64][256]

    const int h = threadIdx.x;
    const int r0 = blockIdx.x * 16;
    const int b = blockIdx.y;
    const int which = blockIdx.z;       // 0 -> query, 1 -> key

    {
        const float4* X4 = (const float4*)((which ? key : query) + ((long)b * LQ + r0) * DD);
        float4* sx4 = (float4*)sx;
        #pragma unroll
        for (int i = h; i < 1024; i += 256) sx4[i] = __ldg(X4 + i);
    }

    float acc[16];
    const float bias = which ? 0.f : __ldg(b1 + h);
    #pragma unroll
    for (int r = 0; r < 16; r++) acc[r] = bias;

    #pragma unroll 1
    for (int dc = 0; dc < 4; dc++) {
        __syncthreads();
        {
            const float4* w4 = (const float4*)(W1 + (long)(which * DD + dc * 64) * HH1);
            float4* sw4 = (float4*)sw;
            #pragma unroll
            for (int i = h; i < 4096; i += 256) sw4[i] = __ldg(w4 + i);
        }
        __syncthreads();

        #pragma unroll
        for (int d4 = 0; d4 < 16; d4++) {
            const int d = dc * 64 + d4 * 4;
            const float w0 = sw[(d4 * 4 + 0) * 256 + h];
            const float w1 = sw[(d4 * 4 + 1) * 256 + h];
            const float w2 = sw[(d4 * 4 + 2) * 256 + h];
            const float w3 = sw[(d4 * 4 + 3) * 256 + h];
            #pragma unroll
            for (int r = 0; r < 16; r++) {
                float4 xv = *(const float4*)(sx + r * 256 + d);
                acc[r] = fmaf(xv.x, w0, acc[r]);
                acc[r] = fmaf(xv.y, w1, acc[r]);
                acc[r] = fmaf(xv.z, w2, acc[r]);
                acc[r] = fmaf(xv.w, w3, acc[r]);
            }
        }
    }

    float* dst = (which ? g_kp : g_qp) + ((long)b * LQ + r0) * HH1 + hperm(h);
    #pragma unroll
    for (int r = 0; r < 16; r++) dst[(long)r * HH1] = acc[r];
}

// ---------------------------------------------------------------------------
// Kernel 2: fused MLP scores via mma.sync m16n8k16 bf16.
// CTA = 256 pairs (M) x 128 j (N), K = 256 (h).  512 threads / 16 warps.
// Warp tile M=32 x N=64 (2 mt x 8 nt) -- minimizes redundant A-generation.
// ---------------------------------------------------------------------------
#define OFF_W2B   0                    // bytes: bf16 [128][272] = 69632
#define OFF_QPB   69632                // fp32 [16][272] = 17408
#define OFF_KPB   87040                // fp32 [16][272]
#define OFF_BWB   104448               // float2[128]
#define OFF_PARTB 105472               // float[2*256]
#define SMEM_BYTES 107520

__device__ __forceinline__ uint32_t pack_relu_bf16(float lo, float hi) {
    uint32_t r;
    asm("cvt.rn.bf16x2.f32 %0, %1, %2;" : "=r"(r) : "f"(hi), "f"(lo));
    asm("max.bf16x2 %0, %0, %1;" : "+r"(r) : "r"(0u));
    return r;
}

__device__ __forceinline__ void mma_bf16(float* c, const uint32_t* a, const uint32_t* b) {
    asm volatile(
        "mma.sync.aligned.m16n8k16.row.col.f32.bf16.bf16.f32 "
        "{%0,%1,%2,%3}, {%4,%5,%6,%7}, {%8,%9}, {%0,%1,%2,%3};"
        : "+f"(c[0]), "+f"(c[1]), "+f"(c[2]), "+f"(c[3])
        : "r"(a[0]), "r"(a[1]), "r"(a[2]), "r"(a[3]), "r"(b[0]), "r"(b[1]));
}

__global__ void __launch_bounds__(512, 1)
score_mma_kernel(const float* __restrict__ b2, const float* __restrict__ W3,
                 const float* __restrict__ b3, float* __restrict__ scores) {
    extern __shared__ char smem[];
    float* smemf = (float*)smem;
    const int tid = threadIdx.x;
    const int k0blk = blockIdx.x * 16, q0blk = blockIdx.y * 16, b = blockIdx.z;

    // ---- cooperative staging ----
    {
        uint4* dW = (uint4*)(smem + OFF_W2B);
        #pragma unroll 4
        for (int i = tid; i < 4352; i += 512) dW[i] = g_w2bt4[i];

        const float4* gq = (const float4*)(g_qp + ((long)b * LQ + q0blk) * HH1);
        const float4* gk = (const float4*)(g_kp + ((long)b * LK + k0blk) * HH1);
        float4* dq = (float4*)(smem + OFF_QPB);
        float4* dk = (float4*)(smem + OFF_KPB);
        #pragma unroll
        for (int i4 = tid; i4 < 1024; i4 += 512) {
            int r = i4 >> 6, c = i4 & 63;
            dq[r * 68 + c] = __ldg(gq + i4);
            dk[r * 68 + c] = __ldg(gk + i4);
        }
        if (tid < HH2)
            ((float2*)(smem + OFF_BWB))[tid] = make_float2(__ldg(b2 + tid), __ldg(W3 + tid));
    }
    __syncthreads();

    const int w = tid >> 5, lane = tid & 31;
    const int mwarp = w & 7;        // M offset = mwarp*32
    const int nwarp = w >> 3;       // N offset = nwarp*64
    const int n0 = nwarp * 64;
    const int lr = lane >> 2, lc = lane & 3;

    float acc[2][8][4];
    #pragma unroll
    for (int mt = 0; mt < 2; mt++)
        #pragma unroll
        for (int nt = 0; nt < 8; nt++)
            #pragma unroll
            for (int c = 0; c < 4; c++) acc[mt][nt][c] = 0.f;

    const float* kpA = smemf + OFF_KPB / 4 + lr * 272 + 4 * lc;
    const float* kpB = kpA + 8 * 272;
    const float* qpb = smemf + OFF_QPB / 4 + (mwarp * 2) * 272 + 4 * lc;
    const uint16_t* w2p = (const uint16_t*)(smem + OFF_W2B) + (n0 + lr) * 272 + 4 * lc;

    #pragma unroll 4
    for (int c = 0; c < 16; c++) {
        const int hb = c * 16;
        const float4 kA = *(const float4*)(kpA + hb);
        const float4 kB = *(const float4*)(kpB + hb);
        uint2 bfr[8];
        #pragma unroll
        for (int nt = 0; nt < 8; nt++)
            bfr[nt] = *(const uint2*)(w2p + nt * (8 * 272) + hb);

        #pragma unroll
        for (int mt = 0; mt < 2; mt++) {
            const float4 q4 = *(const float4*)(qpb + mt * 272 + hb);
            uint32_t a[4];
            a[0] = pack_relu_bf16(q4.x + kA.x, q4.y + kA.y);   // row lr,   k 2lc,2lc+1
            a[1] = pack_relu_bf16(q4.x + kB.x, q4.y + kB.y);   // row lr+8, k 2lc,2lc+1
            a[2] = pack_relu_bf16(q4.z + kA.z, q4.w + kA.w);   // row lr,   k 2lc+8,9
            a[3] = pack_relu_bf16(q4.z + kB.z, q4.w + kB.w);   // row lr+8, k 2lc+8,9
            #pragma unroll
            for (int nt = 0; nt < 8; nt++)
                mma_bf16(acc[mt][nt], a, (const uint32_t*)&bfr[nt]);
        }
    }

    // ---- epilogue: score(p) = b3 + sum_j relu(D[p][j]+b2[j])*W3[j] ----
    const float2* bw = (const float2*)(smem + OFF_BWB);
    float* part = smemf + OFF_PARTB / 4;

    float s0[2], s1[2];
    #pragma unroll
    for (int mt = 0; mt < 2; mt++) {
        float t0 = 0.f, t1 = 0.f;
        #pragma unroll
        for (int nt = 0; nt < 8; nt++) {
            const int jj = n0 + nt * 8 + 2 * lc;
            float2 cA = bw[jj];
            float2 cB = bw[jj + 1];
            t0 = fmaf(fmaxf(acc[mt][nt][0] + cA.x, 0.f), cA.y, t0);
            t0 = fmaf(fmaxf(acc[mt][nt][1] + cB.x, 0.f), cB.y, t0);
            t1 = fmaf(fmaxf(acc[mt][nt][2] + cA.x, 0.f), cA.y, t1);
            t1 = fmaf(fmaxf(acc[mt][nt][3] + cB.x, 0.f), cB.y, t1);
        }
        s0[mt] = t0; s1[mt] = t1;
    }
    #pragma unroll
    for (int off = 1; off < 4; off <<= 1)
        #pragma unroll
        for (int mt = 0; mt < 2; mt++) {
            s0[mt] += __shfl_xor_sync(0xffffffffu, s0[mt], off);
            s1[mt] += __shfl_xor_sync(0xffffffffu, s1[mt], off);
        }

    if (lc == 0) {
        #pragma unroll
        for (int mt = 0; mt < 2; mt++) {
            part[nwarp * 256 + (mwarp * 2 + mt) * 16 + lr]     = s0[mt];
            part[nwarp * 256 + (mwarp * 2 + mt) * 16 + lr + 8] = s1[mt];
        }
    }
    __syncthreads();
    if (tid < 256) {
        const float bb3 = __ldg(b3);
        const int p = tid;
        float f = part[p] + part[256 + p] + bb3;
        const int q = q0blk + (p >> 4);
        scores[((long)b * LQ + q) * LK + k0blk + (p & 15)] = f;
    }
}

// ---------------------------------------------------------------------------
// Kernel 3: mask + softmax over k (warp-per-row), writes attn in place.
// ---------------------------------------------------------------------------
__global__ void __launch_bounds__(256, 2)
softmax_kernel(const int* __restrict__ mask, float* __restrict__ attn) {
    const int b = blockIdx.y;
    const int q0 = blockIdx.x * 8;
    const int tid = threadIdx.x;
    const int w = tid >> 5, lane = tid & 31;

    const long rowbase = ((long)b * LQ + q0 + w) * LK;
    float vals[16];
    float mx = -3.4e38f;
    #pragma unroll
    for (int i = 0; i < 16; i++) {
        int k = lane + i * 32;
        float s = attn[rowbase + k];
        if (__ldg(mask + rowbase + k) == 0) s = -1e9f;
        vals[i] = s;
        mx = fmaxf(mx, s);
    }
    #pragma unroll
    for (int off = 16; off > 0; off >>= 1)
        mx = fmaxf(mx, __shfl_xor_sync(0xffffffffu, mx, off));

    float sum = 0.f;
    #pragma unroll
    for (int i = 0; i < 16; i++) {
        vals[i] = __expf(vals[i] - mx);
        sum += vals[i];
    }
    #pragma unroll
    for (int off = 16; off > 0; off >>= 1)
        sum += __shfl_xor_sync(0xffffffffu, sum, off);
    const float inv = 1.f / sum;

    #pragma unroll
    for (int i = 0; i < 16; i++)
        attn[rowbase + lane + i * 32] = vals[i] * inv;
}

// ---------------------------------------------------------------------------
// Kernel 4: AV partials.  Block = (8 q-rows, 1 k-split of 128, b).
// ---------------------------------------------------------------------------
__global__ void __launch_bounds__(256, 4)
av_kernel(const float* __restrict__ value, const float* __restrict__ attn) {
    __shared__ float sa[8][128];
    const int q0 = blockIdx.x * 8;
    const int ks = blockIdx.y;
    const int b = blockIdx.z;
    const int tid = threadIdx.x;

    #pragma unroll
    for (int i = tid; i < 1024; i += 256) {
        int r = i >> 7, k = i & 127;
        sa[r][k] = attn[((long)b * LQ + q0 + r) * LK + ks * 128 + k];
    }
    __syncthreads();

    const int d = tid;
    float acc[8] = {0.f, 0.f, 0.f, 0.f, 0.f, 0.f, 0.f, 0.f};
    const float* Vb = value + ((long)b * LK + ks * 128) * DD + d;
    #pragma unroll 8
    for (int k = 0; k < 128; k++) {
        float v = __ldg(Vb + (long)k * DD);
        #pragma unroll
        for (int r = 0; r < 8; r++) acc[r] = fmaf(sa[r][k], v, acc[r]);
    }

    float* dst = g_av + (long)ks * (BB * LQ * DD) + ((long)b * LQ + q0) * DD + d;
    #pragma unroll
    for (int r = 0; r < 8; r++) dst[(long)r * DD] = acc[r];
}

// ---------------------------------------------------------------------------
// Kernel 5: reduce the KSPLIT partials into out.
// ---------------------------------------------------------------------------
__global__ void __launch_bounds__(256, 4)
av_reduce_kernel(float* __restrict__ out) {
    const int i = blockIdx.x * 256 + threadIdx.x;     // float4 index
    const float4* p0 = (const float4*)g_av;
    float4 a = p0[i];
    float4 c = p0[i + 65536];
    float4 d = p0[i + 131072];
    float4 e = p0[i + 196608];
    float4 r;
    r.x = a.x + c.x + d.x + e.x;
    r.y = a.y + c.y + d.y + e.y;
    r.z = a.z + c.z + d.z + e.z;
    r.w = a.w + c.w + d.w + e.w;
    ((float4*)out)[i] = r;
}

// ---------------------------------------------------------------------------
extern "C" void kernel_launch(void* const* d_in, const int* in_sizes, int n_in,
                              void* d_out, int out_size) {
    const float* query = (const float*)d_in[0];
    const float* key   = (const float*)d_in[1];
    const float* value = (const float*)d_in[2];
    const int*   mask  = (const int*)d_in[3];
    const float* W1 = (const float*)d_in[4];
    const float* b1 = (const float*)d_in[5];
    const float* W2 = (const float*)d_in[6];
    const float* b2 = (const float*)d_in[7];
    const float* W3 = (const float*)d_in[8];
    const float* b3 = (const float*)d_in[9];

    float* out  = (float*)d_out;                 // [B, LQ, D]
    float* attn = out + (long)BB * LQ * DD;      // [B, LQ, LK]

    cudaFuncSetAttribute(proj_kernel,
                         cudaFuncAttributeMaxDynamicSharedMemorySize, PROJ_SMEM);
    cudaFuncSetAttribute(score_mma_kernel,
                         cudaFuncAttributeMaxDynamicSharedMemorySize, SMEM_BYTES);

    w2bt_kernel<<<128, 256>>>(W2);
    proj_kernel<<<dim3(LQ / 16, BB, 2), 256, PROJ_SMEM>>>(query, key, W1, b1);
    score_mma_kernel<<<dim3(LK / 16, LQ / 16, BB), 512, SMEM_BYTES>>>(b2, W3, b3, attn);
    softmax_kernel<<<dim3(LQ / 8, BB), 256>>>(mask, attn);
    av_kernel<<<dim3(LQ / 8, KSPLIT, BB), 256>>>(value, attn);
    av_reduce_kernel<<<256, 256>>>(out);
}

// round 8
// speedup vs baseline: 1.7235x; 1.0473x over previous
#include <cuda_runtime.h>
#include <cuda_bf16.h>
#include <cstdint>

#define LQ 512
#define LK 512
#define DD 256
#define HH1 256
#define HH2 128
#define BB 2
#define KSPLIT 8

// global scratch: projections [b][row][h_perm] (h contiguous, permuted within 16)
__device__ float g_qp[BB * LQ * HH1];
__device__ float g_kp[BB * LK * HH1];
// W2^T, bf16, [j=128][h_perm stride 272]
__device__ uint4 g_w2bt4[4352];
// AV partial sums [ks][b][q][d]
__device__ float g_av[KSPLIT * BB * LQ * DD];

// perm within 16-block: orig o -> pos ((o&6)<<1) + (o&1) + ((o&8)>>2)
__device__ __forceinline__ int hperm(int h) {
    int o = h & 15;
    return (h & ~15) + ((o & 6) << 1) + (o & 1) + ((o & 8) >> 2);
}

// ---------------------------------------------------------------------------
// Kernel 0: W2 [h][j] -> g_w2bt4 bf16 [j][perm(h)], row stride 272
// ---------------------------------------------------------------------------
__global__ void w2bt_kernel(const float* __restrict__ W2) {
    int idx = blockIdx.x * 256 + threadIdx.x;   // 32768 = 256h * 128j
    int j = idx & 127, h = idx >> 7;
    float v = __ldg(W2 + h * HH2 + j);
    __nv_bfloat16 bv = __float2bfloat16(v);
    ((uint16_t*)g_w2bt4)[j * 272 + hperm(h)] = *(uint16_t*)&bv;
}

// ---------------------------------------------------------------------------
// Kernel 1: projections via mma.sync tf32 m16n8k8.
// CTA = 16 rows x 256 h, K = 256 d.  512 threads / 16 warps.
// Warp w: N-slice h = [w*16, w*16+16) (2 nt of 8), M = all 16 rows (1 mt).
// ---------------------------------------------------------------------------
#define SXP 260                          // X smem stride (floats)
#define SWP 264                          // W1 chunk smem stride (floats)
#define PM_SMEM ((16 * SXP + 64 * SWP) * 4)   // ~84.2 KB

__device__ __forceinline__ void mma_tf32(float* c, const float* a, const float* b) {
    asm volatile(
        "mma.sync.aligned.m16n8k8.row.col.f32.tf32.tf32.f32 "
        "{%0,%1,%2,%3}, {%4,%5,%6,%7}, {%8,%9}, {%0,%1,%2,%3};"
        : "+f"(c[0]), "+f"(c[1]), "+f"(c[2]), "+f"(c[3])
        : "r"(__float_as_uint(a[0])), "r"(__float_as_uint(a[1])),
          "r"(__float_as_uint(a[2])), "r"(__float_as_uint(a[3])),
          "r"(__float_as_uint(b[0])), "r"(__float_as_uint(b[1])));
}

__global__ void __launch_bounds__(512, 1)
proj_mma_kernel(const float* __restrict__ query,
                const float* __restrict__ key,
                const float* __restrict__ W1,
                const float* __restrict__ b1) {
    extern __shared__ float psm[];
    float* sx = psm;               // [16][SXP]
    float* sw1 = psm + 16 * SXP;   // [64][SWP]

    const int tid = threadIdx.x;
    const int row0 = blockIdx.x * 16;
    const int b = blockIdx.y;
    const int which = blockIdx.z;        // 0 -> query/qp, 1 -> key/kp

    // stage X tile [16][256]
    {
        const float4* X4 = (const float4*)((which ? key : query) + ((long)b * LQ + row0) * DD);
        #pragma unroll
        for (int i4 = tid; i4 < 1024; i4 += 512) {
            int r = i4 >> 6, c = i4 & 63;
            *(float4*)(sx + r * SXP + c * 4) = __ldg(X4 + i4);
        }
    }

    const int w = tid >> 5, lane = tid & 31;
    const int lr = lane >> 2, lc = lane & 3;
    const int n0 = w * 16;

    float acc[2][4];
    #pragma unroll
    for (int nt = 0; nt < 2; nt++)
        #pragma unroll
        for (int c = 0; c < 4; c++) acc[nt][c] = 0.f;

    #pragma unroll 1
    for (int dc = 0; dc < 4; dc++) {
        __syncthreads();
        {   // stage W1 chunk [64 d][256 h]
            const float4* w4 = (const float4*)(W1 + (long)(which * DD + dc * 64) * HH1);
            #pragma unroll
            for (int i4 = tid; i4 < 4096; i4 += 512) {
                int dd = i4 >> 6, c = i4 & 63;
                *(float4*)(sw1 + dd * SWP + c * 4) = __ldg(w4 + i4);
            }
        }
        __syncthreads();

        #pragma unroll
        for (int kc = 0; kc < 8; kc++) {
            const int kg = dc * 64 + kc * 8;          // global d for A (in sx)
            const int kl = kc * 8;                    // local d for B (in sw1)
            float a[4];
            a[0] = sx[lr * SXP + kg + lc];
            a[1] = sx[(lr + 8) * SXP + kg + lc];
            a[2] = sx[lr * SXP + kg + lc + 4];
            a[3] = sx[(lr + 8) * SXP + kg + lc + 4];
            #pragma unroll
            for (int nt = 0; nt < 2; nt++) {
                float bf[2];
                bf[0] = sw1[(kl + lc) * SWP + n0 + nt * 8 + lr];
                bf[1] = sw1[(kl + lc + 4) * SWP + n0 + nt * 8 + lr];
                mma_tf32(acc[nt], a, bf);
            }
        }
    }

    // epilogue: D(lr, 2lc) etc; add b1 (q only), write permuted h
    float* dstb = (which ? g_kp : g_qp) + ((long)b * LQ + row0) * HH1;
    #pragma unroll
    for (int nt = 0; nt < 2; nt++) {
        const int n = n0 + nt * 8 + 2 * lc;
        const float bb0 = which ? 0.f : __ldg(b1 + n);
        const float bb1 = which ? 0.f : __ldg(b1 + n + 1);
        const int hp0 = hperm(n), hp1 = hperm(n + 1);
        dstb[(long)lr * HH1 + hp0]       = acc[nt][0] + bb0;
        dstb[(long)lr * HH1 + hp1]       = acc[nt][1] + bb1;
        dstb[(long)(lr + 8) * HH1 + hp0] = acc[nt][2] + bb0;
        dstb[(long)(lr + 8) * HH1 + hp1] = acc[nt][3] + bb1;
    }
}

// ---------------------------------------------------------------------------
// Kernel 2: fused MLP scores via mma.sync m16n8k16 bf16.  (unchanged from R7)
// ---------------------------------------------------------------------------
#define OFF_W2B   0                    // bytes: bf16 [128][272] = 69632
#define OFF_QPB   69632                // fp32 [16][272] = 17408
#define OFF_KPB   87040                // fp32 [16][272]
#define OFF_BWB   104448               // float2[128]
#define OFF_PARTB 105472               // float[2*256]
#define SMEM_BYTES 107520

__device__ __forceinline__ uint32_t pack_relu_bf16(float lo, float hi) {
    uint32_t r;
    asm("cvt.rn.bf16x2.f32 %0, %1, %2;" : "=r"(r) : "f"(hi), "f"(lo));
    asm("max.bf16x2 %0, %0, %1;" : "+r"(r) : "r"(0u));
    return r;
}

__device__ __forceinline__ void mma_bf16(float* c, const uint32_t* a, const uint32_t* b) {
    asm volatile(
        "mma.sync.aligned.m16n8k16.row.col.f32.bf16.bf16.f32 "
        "{%0,%1,%2,%3}, {%4,%5,%6,%7}, {%8,%9}, {%0,%1,%2,%3};"
        : "+f"(c[0]), "+f"(c[1]), "+f"(c[2]), "+f"(c[3])
        : "r"(a[0]), "r"(a[1]), "r"(a[2]), "r"(a[3]), "r"(b[0]), "r"(b[1]));
}

__global__ void __launch_bounds__(512, 1)
score_mma_kernel(const float* __restrict__ b2, const float* __restrict__ W3,
                 const float* __restrict__ b3, float* __restrict__ scores) {
    extern __shared__ char smem[];
    float* smemf = (float*)smem;
    const int tid = threadIdx.x;
    const int k0blk = blockIdx.x * 16, q0blk = blockIdx.y * 16, b = blockIdx.z;

    {
        uint4* dW = (uint4*)(smem + OFF_W2B);
        #pragma unroll 4
        for (int i = tid; i < 4352; i += 512) dW[i] = g_w2bt4[i];

        const float4* gq = (const float4*)(g_qp + ((long)b * LQ + q0blk) * HH1);
        const float4* gk = (const float4*)(g_kp + ((long)b * LK + k0blk) * HH1);
        float4* dq = (float4*)(smem + OFF_QPB);
        float4* dk = (float4*)(smem + OFF_KPB);
        #pragma unroll
        for (int i4 = tid; i4 < 1024; i4 += 512) {
            int r = i4 >> 6, c = i4 & 63;
            dq[r * 68 + c] = __ldg(gq + i4);
            dk[r * 68 + c] = __ldg(gk + i4);
        }
        if (tid < HH2)
            ((float2*)(smem + OFF_BWB))[tid] = make_float2(__ldg(b2 + tid), __ldg(W3 + tid));
    }
    __syncthreads();

    const int w = tid >> 5, lane = tid & 31;
    const int mwarp = w & 7;        // M offset = mwarp*32
    const int nwarp = w >> 3;       // N offset = nwarp*64
    const int n0 = nwarp * 64;
    const int lr = lane >> 2, lc = lane & 3;

    float acc[2][8][4];
    #pragma unroll
    for (int mt = 0; mt < 2; mt++)
        #pragma unroll
        for (int nt = 0; nt < 8; nt++)
            #pragma unroll
            for (int c = 0; c < 4; c++) acc[mt][nt][c] = 0.f;

    const float* kpA = smemf + OFF_KPB / 4 + lr * 272 + 4 * lc;
    const float* kpB = kpA + 8 * 272;
    const float* qpb = smemf + OFF_QPB / 4 + (mwarp * 2) * 272 + 4 * lc;
    const uint16_t* w2p = (const uint16_t*)(smem + OFF_W2B) + (n0 + lr) * 272 + 4 * lc;

    #pragma unroll 4
    for (int c = 0; c < 16; c++) {
        const int hb = c * 16;
        const float4 kA = *(const float4*)(kpA + hb);
        const float4 kB = *(const float4*)(kpB + hb);
        uint2 bfr[8];
        #pragma unroll
        for (int nt = 0; nt < 8; nt++)
            bfr[nt] = *(const uint2*)(w2p + nt * (8 * 272) + hb);

        #pragma unroll
        for (int mt = 0; mt < 2; mt++) {
            const float4 q4 = *(const float4*)(qpb + mt * 272 + hb);
            uint32_t a[4];
            a[0] = pack_relu_bf16(q4.x + kA.x, q4.y + kA.y);
            a[1] = pack_relu_bf16(q4.x + kB.x, q4.y + kB.y);
            a[2] = pack_relu_bf16(q4.z + kA.z, q4.w + kA.w);
            a[3] = pack_relu_bf16(q4.z + kB.z, q4.w + kB.w);
            #pragma unroll
            for (int nt = 0; nt < 8; nt++)
                mma_bf16(acc[mt][nt], a, (const uint32_t*)&bfr[nt]);
        }
    }

    const float2* bw = (const float2*)(smem + OFF_BWB);
    float* part = smemf + OFF_PARTB / 4;

    float s0[2], s1[2];
    #pragma unroll
    for (int mt = 0; mt < 2; mt++) {
        float t0 = 0.f, t1 = 0.f;
        #pragma unroll
        for (int nt = 0; nt < 8; nt++) {
            const int jj = n0 + nt * 8 + 2 * lc;
            float2 cA = bw[jj];
            float2 cB = bw[jj + 1];
            t0 = fmaf(fmaxf(acc[mt][nt][0] + cA.x, 0.f), cA.y, t0);
            t0 = fmaf(fmaxf(acc[mt][nt][1] + cB.x, 0.f), cB.y, t0);
            t1 = fmaf(fmaxf(acc[mt][nt][2] + cA.x, 0.f), cA.y, t1);
            t1 = fmaf(fmaxf(acc[mt][nt][3] + cB.x, 0.f), cB.y, t1);
        }
        s0[mt] = t0; s1[mt] = t1;
    }
    #pragma unroll
    for (int off = 1; off < 4; off <<= 1)
        #pragma unroll
        for (int mt = 0; mt < 2; mt++) {
            s0[mt] += __shfl_xor_sync(0xffffffffu, s0[mt], off);
            s1[mt] += __shfl_xor_sync(0xffffffffu, s1[mt], off);
        }

    if (lc == 0) {
        #pragma unroll
        for (int mt = 0; mt < 2; mt++) {
            part[nwarp * 256 + (mwarp * 2 + mt) * 16 + lr]     = s0[mt];
            part[nwarp * 256 + (mwarp * 2 + mt) * 16 + lr + 8] = s1[mt];
        }
    }
    __syncthreads();
    if (tid < 256) {
        const float bb3 = __ldg(b3);
        const int p = tid;
        float f = part[p] + part[256 + p] + bb3;
        const int q = q0blk + (p >> 4);
        scores[((long)b * LQ + q) * LK + k0blk + (p & 15)] = f;
    }
}

// ---------------------------------------------------------------------------
// Kernel 3: mask + softmax over k (warp-per-row), writes attn in place.
// ---------------------------------------------------------------------------
__global__ void __launch_bounds__(256, 2)
softmax_kernel(const int* __restrict__ mask, float* __restrict__ attn) {
    const int b = blockIdx.y;
    const int q0 = blockIdx.x * 8;
    const int tid = threadIdx.x;
    const int w = tid >> 5, lane = tid & 31;

    const long rowbase = ((long)b * LQ + q0 + w) * LK;
    float vals[16];
    float mx = -3.4e38f;
    #pragma unroll
    for (int i = 0; i < 16; i++) {
        int k = lane + i * 32;
        float s = attn[rowbase + k];
        if (__ldg(mask + rowbase + k) == 0) s = -1e9f;
        vals[i] = s;
        mx = fmaxf(mx, s);
    }
    #pragma unroll
    for (int off = 16; off > 0; off >>= 1)
        mx = fmaxf(mx, __shfl_xor_sync(0xffffffffu, mx, off));

    float sum = 0.f;
    #pragma unroll
    for (int i = 0; i < 16; i++) {
        vals[i] = __expf(vals[i] - mx);
        sum += vals[i];
    }
    #pragma unroll
    for (int off = 16; off > 0; off >>= 1)
        sum += __shfl_xor_sync(0xffffffffu, sum, off);
    const float inv = 1.f / sum;

    #pragma unroll
    for (int i = 0; i < 16; i++)
        attn[rowbase + lane + i * 32] = vals[i] * inv;
}

// ---------------------------------------------------------------------------
// Kernel 4: AV partials.  Block = (8 q-rows, 1 k-split of 64, b).
// ---------------------------------------------------------------------------
__global__ void __launch_bounds__(256, 4)
av_kernel(const float* __restrict__ value, const float* __restrict__ attn) {
    __shared__ float sa[8][64];
    const int q0 = blockIdx.x * 8;
    const int ks = blockIdx.y;
    const int b = blockIdx.z;
    const int tid = threadIdx.x;

    #pragma unroll
    for (int i = tid; i < 512; i += 256) {
        int r = i >> 6, k = i & 63;
        sa[r][k] = attn[((long)b * LQ + q0 + r) * LK + ks * 64 + k];
    }
    __syncthreads();

    const int d = tid;
    float acc[8] = {0.f, 0.f, 0.f, 0.f, 0.f, 0.f, 0.f, 0.f};
    const float* Vb = value + ((long)b * LK + ks * 64) * DD + d;
    #pragma unroll 8
    for (int k = 0; k < 64; k++) {
        float v = __ldg(Vb + (long)k * DD);
        #pragma unroll
        for (int r = 0; r < 8; r++) acc[r] = fmaf(sa[r][k], v, acc[r]);
    }

    float* dst = g_av + (long)ks * (BB * LQ * DD) + ((long)b * LQ + q0) * DD + d;
    #pragma unroll
    for (int r = 0; r < 8; r++) dst[(long)r * DD] = acc[r];
}

// ---------------------------------------------------------------------------
// Kernel 5: reduce the KSPLIT partials into out.
// ---------------------------------------------------------------------------
__global__ void __launch_bounds__(256, 4)
av_reduce_kernel(float* __restrict__ out) {
    const int i = blockIdx.x * 256 + threadIdx.x;     // float4 index
    const float4* p0 = (const float4*)g_av;
    float4 r = p0[i];
    #pragma unroll
    for (int j = 1; j < KSPLIT; j++) {
        float4 a = p0[i + j * 65536];
        r.x += a.x; r.y += a.y; r.z += a.z; r.w += a.w;
    }
    ((float4*)out)[i] = r;
}

// ---------------------------------------------------------------------------
extern "C" void kernel_launch(void* const* d_in, const int* in_sizes, int n_in,
                              void* d_out, int out_size) {
    const float* query = (const float*)d_in[0];
    const float* key   = (const float*)d_in[1];
    const float* value = (const float*)d_in[2];
    const int*   mask  = (const int*)d_in[3];
    const float* W1 = (const float*)d_in[4];
    const float* b1 = (const float*)d_in[5];
    const float* W2 = (const float*)d_in[6];
    const float* b2 = (const float*)d_in[7];
    const float* W3 = (const float*)d_in[8];
    const float* b3 = (const float*)d_in[9];

    float* out  = (float*)d_out;                 // [B, LQ, D]
    float* attn = out + (long)BB * LQ * DD;      // [B, LQ, LK]

    cudaFuncSetAttribute(proj_mma_kernel,
                         cudaFuncAttributeMaxDynamicSharedMemorySize, PM_SMEM);
    cudaFuncSetAttribute(score_mma_kernel,
                         cudaFuncAttributeMaxDynamicSharedMemorySize, SMEM_BYTES);

    w2bt_kernel<<<128, 256>>>(W2);
    proj_mma_kernel<<<dim3(LQ / 16, BB, 2), 512, PM_SMEM>>>(query, key, W1, b1);
    score_mma_kernel<<<dim3(LK / 16, LQ / 16, BB), 512, SMEM_BYTES>>>(b2, W3, b3, attn);
    softmax_kernel<<<dim3(LQ / 8, BB), 256>>>(mask, attn);
    av_kernel<<<dim3(LQ / 8, KSPLIT, BB), 256>>>(value, attn);
    av_reduce_kernel<<<256, 256>>>(out);
}

// round 9
// speedup vs baseline: 1.9461x; 1.1291x over previous
#include <cuda_runtime.h>
#include <cuda_bf16.h>
#include <cstdint>

#define LQ 512
#define LK 512
#define DD 256
#define HH1 256
#define HH2 128
#define BB 2
#define KSPLIT 8
#define NTILES 2048      // 32 k-tiles * 32 q-tiles * 2 b
#define SGRID 148

// global scratch: projections [b][row][h_perm] (h contiguous, permuted within 16)
__device__ float g_qp[BB * LQ * HH1];
__device__ float g_kp[BB * LK * HH1];
// W2^T, bf16, [j=128][h_perm stride 272]
__device__ uint4 g_w2bt4[4352];
// AV partial sums [ks][b][q][d]
__device__ float g_av[KSPLIT * BB * LQ * DD];

// perm within 16-block: orig o -> pos ((o&6)<<1) + (o&1) + ((o&8)>>2)
__device__ __forceinline__ int hperm(int h) {
    int o = h & 15;
    return (h & ~15) + ((o & 6) << 1) + (o & 1) + ((o & 8) >> 2);
}

__device__ __forceinline__ uint32_t smem_addr(const void* p) {
    return (uint32_t)__cvta_generic_to_shared(p);
}
__device__ __forceinline__ void cp_async16(uint32_t saddr, const void* gaddr) {
    asm volatile("cp.async.cg.shared.global [%0], [%1], 16;" :: "r"(saddr), "l"(gaddr));
}
#define CP_COMMIT() asm volatile("cp.async.commit_group;" ::: "memory")
#define CP_WAIT1()  asm volatile("cp.async.wait_group 1;" ::: "memory")
#define CP_WAIT0()  asm volatile("cp.async.wait_group 0;" ::: "memory")

// ---------------------------------------------------------------------------
// Kernel 0: W2 [h][j] -> g_w2bt4 bf16 [j][perm(h)], row stride 272
// ---------------------------------------------------------------------------
__global__ void w2bt_kernel(const float* __restrict__ W2) {
    int idx = blockIdx.x * 256 + threadIdx.x;   // 32768 = 256h * 128j
    int j = idx & 127, h = idx >> 7;
    float v = __ldg(W2 + h * HH2 + j);
    __nv_bfloat16 bv = __float2bfloat16(v);
    ((uint16_t*)g_w2bt4)[j * 272 + hperm(h)] = *(uint16_t*)&bv;
}

// ---------------------------------------------------------------------------
// Kernel 1: projections via mma.sync tf32 m16n8k8.
// ---------------------------------------------------------------------------
#define SXP 260
#define SWP 264
#define PM_SMEM ((16 * SXP + 64 * SWP) * 4)

__device__ __forceinline__ void mma_tf32(float* c, const float* a, const float* b) {
    asm volatile(
        "mma.sync.aligned.m16n8k8.row.col.f32.tf32.tf32.f32 "
        "{%0,%1,%2,%3}, {%4,%5,%6,%7}, {%8,%9}, {%0,%1,%2,%3};"
        : "+f"(c[0]), "+f"(c[1]), "+f"(c[2]), "+f"(c[3])
        : "r"(__float_as_uint(a[0])), "r"(__float_as_uint(a[1])),
          "r"(__float_as_uint(a[2])), "r"(__float_as_uint(a[3])),
          "r"(__float_as_uint(b[0])), "r"(__float_as_uint(b[1])));
}

__global__ void __launch_bounds__(512, 1)
proj_mma_kernel(const float* __restrict__ query,
                const float* __restrict__ key,
                const float* __restrict__ W1,
                const float* __restrict__ b1) {
    extern __shared__ float psm[];
    float* sx = psm;               // [16][SXP]
    float* sw1 = psm + 16 * SXP;   // [64][SWP]

    const int tid = threadIdx.x;
    const int row0 = blockIdx.x * 16;
    const int b = blockIdx.y;
    const int which = blockIdx.z;

    {
        const float4* X4 = (const float4*)((which ? key : query) + ((long)b * LQ + row0) * DD);
        #pragma unroll
        for (int i4 = tid; i4 < 1024; i4 += 512) {
            int r = i4 >> 6, c = i4 & 63;
            *(float4*)(sx + r * SXP + c * 4) = __ldg(X4 + i4);
        }
    }

    const int w = tid >> 5, lane = tid & 31;
    const int lr = lane >> 2, lc = lane & 3;
    const int n0 = w * 16;

    float acc[2][4];
    #pragma unroll
    for (int nt = 0; nt < 2; nt++)
        #pragma unroll
        for (int c = 0; c < 4; c++) acc[nt][c] = 0.f;

    #pragma unroll 1
    for (int dc = 0; dc < 4; dc++) {
        __syncthreads();
        {
            const float4* w4 = (const float4*)(W1 + (long)(which * DD + dc * 64) * HH1);
            #pragma unroll
            for (int i4 = tid; i4 < 4096; i4 += 512) {
                int dd = i4 >> 6, c = i4 & 63;
                *(float4*)(sw1 + dd * SWP + c * 4) = __ldg(w4 + i4);
            }
        }
        __syncthreads();

        #pragma unroll
        for (int kc = 0; kc < 8; kc++) {
            const int kg = dc * 64 + kc * 8;
            const int kl = kc * 8;
            float a[4];
            a[0] = sx[lr * SXP + kg + lc];
            a[1] = sx[(lr + 8) * SXP + kg + lc];
            a[2] = sx[lr * SXP + kg + lc + 4];
            a[3] = sx[(lr + 8) * SXP + kg + lc + 4];
            #pragma unroll
            for (int nt = 0; nt < 2; nt++) {
                float bf[2];
                bf[0] = sw1[(kl + lc) * SWP + n0 + nt * 8 + lr];
                bf[1] = sw1[(kl + lc + 4) * SWP + n0 + nt * 8 + lr];
                mma_tf32(acc[nt], a, bf);
            }
        }
    }

    float* dstb = (which ? g_kp : g_qp) + ((long)b * LQ + row0) * HH1;
    #pragma unroll
    for (int nt = 0; nt < 2; nt++) {
        const int n = n0 + nt * 8 + 2 * lc;
        const float bb0 = which ? 0.f : __ldg(b1 + n);
        const float bb1 = which ? 0.f : __ldg(b1 + n + 1);
        const int hp0 = hperm(n), hp1 = hperm(n + 1);
        dstb[(long)lr * HH1 + hp0]       = acc[nt][0] + bb0;
        dstb[(long)lr * HH1 + hp1]       = acc[nt][1] + bb1;
        dstb[(long)(lr + 8) * HH1 + hp0] = acc[nt][2] + bb0;
        dstb[(long)(lr + 8) * HH1 + hp1] = acc[nt][3] + bb1;
    }
}

// ---------------------------------------------------------------------------
// Kernel 2: PERSISTENT fused MLP score kernel (mma.sync m16n8k16 bf16).
// grid = 148 CTAs; each loops over tiles t = bid, bid+148, ...
// W2 staged once; qp/kp double-buffered via cp.async prefetch.
// ---------------------------------------------------------------------------
#define OFF_W2B   0                    // bf16 [128][272] = 69632 B
#define OFF_QP0   69632                // fp32 [16][272] = 17408 B
#define OFF_KP0   87040
#define OFF_QP1   104448
#define OFF_KP1   121856
#define OFF_BWB   139264               // float2[128] = 1024 B
#define OFF_PARTB 140288               // float[512] = 2048 B
#define SMEM_BYTES 142336

__device__ __forceinline__ uint32_t pack_relu_bf16(float lo, float hi) {
    uint32_t r;
    asm("cvt.rn.bf16x2.f32 %0, %1, %2;" : "=r"(r) : "f"(hi), "f"(lo));
    asm("max.bf16x2 %0, %0, %1;" : "+r"(r) : "r"(0u));
    return r;
}

__device__ __forceinline__ void mma_bf16(float* c, const uint32_t* a, const uint32_t* b) {
    asm volatile(
        "mma.sync.aligned.m16n8k16.row.col.f32.bf16.bf16.f32 "
        "{%0,%1,%2,%3}, {%4,%5,%6,%7}, {%8,%9}, {%0,%1,%2,%3};"
        : "+f"(c[0]), "+f"(c[1]), "+f"(c[2]), "+f"(c[3])
        : "r"(a[0]), "r"(a[1]), "r"(a[2]), "r"(a[3]), "r"(b[0]), "r"(b[1]));
}

__global__ void __launch_bounds__(512, 1)
score_mma_kernel(const float* __restrict__ b2, const float* __restrict__ W3,
                 const float* __restrict__ b3, float* __restrict__ scores) {
    extern __shared__ char smem[];
    float* smemf = (float*)smem;
    const int tid = threadIdx.x;
    const uint32_t sbase = smem_addr(smem);

    // ---- prefetch first tile's qp/kp via cp.async (group 1 pending) ----
    {
        const int t0 = blockIdx.x;
        const int kb = t0 & 31, qb = (t0 >> 5) & 31, b = t0 >> 10;
        const float4* gq = (const float4*)(g_qp + ((long)b * LQ + qb * 16) * HH1);
        const float4* gk = (const float4*)(g_kp + ((long)b * LK + kb * 16) * HH1);
        #pragma unroll
        for (int i4 = tid; i4 < 1024; i4 += 512) {
            int r = i4 >> 6, c = i4 & 63;
            uint32_t off = (uint32_t)(r * 68 + c) * 16;
            cp_async16(sbase + OFF_QP0 + off, gq + i4);
            cp_async16(sbase + OFF_KP0 + off, gk + i4);
        }
        CP_COMMIT();
    }

    // ---- stage W2 (bf16, pre-swizzled) + b2/W3 once ----
    {
        uint4* dW = (uint4*)(smem + OFF_W2B);
        #pragma unroll 4
        for (int i = tid; i < 4352; i += 512) dW[i] = g_w2bt4[i];
        if (tid < HH2)
            ((float2*)(smem + OFF_BWB))[tid] = make_float2(__ldg(b2 + tid), __ldg(W3 + tid));
    }

    const int w = tid >> 5, lane = tid & 31;
    const int mwarp = w & 7;        // M offset = mwarp*32
    const int nwarp = w >> 3;       // N offset = nwarp*64
    const int n0 = nwarp * 64;
    const int lr = lane >> 2, lc = lane & 3;
    const uint16_t* w2p = (const uint16_t*)(smem + OFF_W2B) + (n0 + lr) * 272 + 4 * lc;
    const float2* bw = (const float2*)(smem + OFF_BWB);
    float* part = smemf + OFF_PARTB / 4;
    const float bb3 = __ldg(b3);

    int it = 0;
    #pragma unroll 1
    for (int t = blockIdx.x; t < NTILES; t += SGRID, it++) {
        const int cur = it & 1;
        const int qoff = cur ? OFF_QP1 : OFF_QP0;
        const int koff = cur ? OFF_KP1 : OFF_KP0;

        // prefetch next tile into the other buffer
        const int t2 = t + SGRID;
        if (t2 < NTILES) {
            const int kb2 = t2 & 31, qb2 = (t2 >> 5) & 31, b2i = t2 >> 10;
            const float4* gq = (const float4*)(g_qp + ((long)b2i * LQ + qb2 * 16) * HH1);
            const float4* gk = (const float4*)(g_kp + ((long)b2i * LK + kb2 * 16) * HH1);
            const int qo2 = cur ? OFF_QP0 : OFF_QP1;
            const int ko2 = cur ? OFF_KP0 : OFF_KP1;
            #pragma unroll
            for (int i4 = tid; i4 < 1024; i4 += 512) {
                int r = i4 >> 6, c = i4 & 63;
                uint32_t off = (uint32_t)(r * 68 + c) * 16;
                cp_async16(sbase + qo2 + off, gq + i4);
                cp_async16(sbase + ko2 + off, gk + i4);
            }
            CP_COMMIT();
            CP_WAIT1();
        } else {
            CP_WAIT0();
        }
        __syncthreads();

        const int kb = t & 31, qb = (t >> 5) & 31, b = t >> 10;

        float acc[2][8][4];
        #pragma unroll
        for (int mt = 0; mt < 2; mt++)
            #pragma unroll
            for (int nt = 0; nt < 8; nt++)
                #pragma unroll
                for (int c = 0; c < 4; c++) acc[mt][nt][c] = 0.f;

        const float* kpA = smemf + koff / 4 + lr * 272 + 4 * lc;
        const float* kpB = kpA + 8 * 272;
        const float* qpb = smemf + qoff / 4 + (mwarp * 2) * 272 + 4 * lc;

        #pragma unroll 4
        for (int c = 0; c < 16; c++) {
            const int hb = c * 16;
            const float4 kA = *(const float4*)(kpA + hb);
            const float4 kB = *(const float4*)(kpB + hb);
            uint2 bfr[8];
            #pragma unroll
            for (int nt = 0; nt < 8; nt++)
                bfr[nt] = *(const uint2*)(w2p + nt * (8 * 272) + hb);

            #pragma unroll
            for (int mt = 0; mt < 2; mt++) {
                const float4 q4 = *(const float4*)(qpb + mt * 272 + hb);
                uint32_t a[4];
                a[0] = pack_relu_bf16(q4.x + kA.x, q4.y + kA.y);
                a[1] = pack_relu_bf16(q4.x + kB.x, q4.y + kB.y);
                a[2] = pack_relu_bf16(q4.z + kA.z, q4.w + kA.w);
                a[3] = pack_relu_bf16(q4.z + kB.z, q4.w + kB.w);
                #pragma unroll
                for (int nt = 0; nt < 8; nt++)
                    mma_bf16(acc[mt][nt], a, (const uint32_t*)&bfr[nt]);
            }
        }

        // epilogue: score(p) = b3 + sum_j relu(D[p][j]+b2[j])*W3[j]
        float s0[2], s1[2];
        #pragma unroll
        for (int mt = 0; mt < 2; mt++) {
            float t0 = 0.f, t1 = 0.f;
            #pragma unroll
            for (int nt = 0; nt < 8; nt++) {
                const int jj = n0 + nt * 8 + 2 * lc;
                float2 cA = bw[jj];
                float2 cB = bw[jj + 1];
                t0 = fmaf(fmaxf(acc[mt][nt][0] + cA.x, 0.f), cA.y, t0);
                t0 = fmaf(fmaxf(acc[mt][nt][1] + cB.x, 0.f), cB.y, t0);
                t1 = fmaf(fmaxf(acc[mt][nt][2] + cA.x, 0.f), cA.y, t1);
                t1 = fmaf(fmaxf(acc[mt][nt][3] + cB.x, 0.f), cB.y, t1);
            }
            s0[mt] = t0; s1[mt] = t1;
        }
        #pragma unroll
        for (int off = 1; off < 4; off <<= 1)
            #pragma unroll
            for (int mt = 0; mt < 2; mt++) {
                s0[mt] += __shfl_xor_sync(0xffffffffu, s0[mt], off);
                s1[mt] += __shfl_xor_sync(0xffffffffu, s1[mt], off);
            }

        if (lc == 0) {
            #pragma unroll
            for (int mt = 0; mt < 2; mt++) {
                part[nwarp * 256 + (mwarp * 2 + mt) * 16 + lr]     = s0[mt];
                part[nwarp * 256 + (mwarp * 2 + mt) * 16 + lr + 8] = s1[mt];
            }
        }
        __syncthreads();
        if (tid < 256) {
            const int p = tid;
            float f = part[p] + part[256 + p] + bb3;
            const int q = qb * 16 + (p >> 4);
            scores[((long)b * LQ + q) * LK + kb * 16 + (p & 15)] = f;
        }
    }
}

// ---------------------------------------------------------------------------
// Kernel 3: mask + softmax over k (warp-per-row), writes attn in place.
// ---------------------------------------------------------------------------
__global__ void __launch_bounds__(256, 2)
softmax_kernel(const int* __restrict__ mask, float* __restrict__ attn) {
    const int b = blockIdx.y;
    const int q0 = blockIdx.x * 8;
    const int tid = threadIdx.x;
    const int w = tid >> 5, lane = tid & 31;

    const long rowbase = ((long)b * LQ + q0 + w) * LK;
    float vals[16];
    float mx = -3.4e38f;
    #pragma unroll
    for (int i = 0; i < 16; i++) {
        int k = lane + i * 32;
        float s = attn[rowbase + k];
        if (__ldg(mask + rowbase + k) == 0) s = -1e9f;
        vals[i] = s;
        mx = fmaxf(mx, s);
    }
    #pragma unroll
    for (int off = 16; off > 0; off >>= 1)
        mx = fmaxf(mx, __shfl_xor_sync(0xffffffffu, mx, off));

    float sum = 0.f;
    #pragma unroll
    for (int i = 0; i < 16; i++) {
        vals[i] = __expf(vals[i] - mx);
        sum += vals[i];
    }
    #pragma unroll
    for (int off = 16; off > 0; off >>= 1)
        sum += __shfl_xor_sync(0xffffffffu, sum, off);
    const float inv = 1.f / sum;

    #pragma unroll
    for (int i = 0; i < 16; i++)
        attn[rowbase + lane + i * 32] = vals[i] * inv;
}

// ---------------------------------------------------------------------------
// Kernel 4: AV partials.  Block = (8 q-rows, 1 k-split of 64, b).
// ---------------------------------------------------------------------------
__global__ void __launch_bounds__(256, 4)
av_kernel(const float* __restrict__ value, const float* __restrict__ attn) {
    __shared__ float sa[8][64];
    const int q0 = blockIdx.x * 8;
    const int ks = blockIdx.y;
    const int b = blockIdx.z;
    const int tid = threadIdx.x;

    #pragma unroll
    for (int i = tid; i < 512; i += 256) {
        int r = i >> 6, k = i & 63;
        sa[r][k] = attn[((long)b * LQ + q0 + r) * LK + ks * 64 + k];
    }
    __syncthreads();

    const int d = tid;
    float acc[8] = {0.f, 0.f, 0.f, 0.f, 0.f, 0.f, 0.f, 0.f};
    const float* Vb = value + ((long)b * LK + ks * 64) * DD + d;
    #pragma unroll 8
    for (int k = 0; k < 64; k++) {
        float v = __ldg(Vb + (long)k * DD);
        #pragma unroll
        for (int r = 0; r < 8; r++) acc[r] = fmaf(sa[r][k], v, acc[r]);
    }

    float* dst = g_av + (long)ks * (BB * LQ * DD) + ((long)b * LQ + q0) * DD + d;
    #pragma unroll
    for (int r = 0; r < 8; r++) dst[(long)r * DD] = acc[r];
}

// ---------------------------------------------------------------------------
// Kernel 5: reduce the KSPLIT partials into out.
// ---------------------------------------------------------------------------
__global__ void __launch_bounds__(256, 4)
av_reduce_kernel(float* __restrict__ out) {
    const int i = blockIdx.x * 256 + threadIdx.x;     // float4 index
    const float4* p0 = (const float4*)g_av;
    float4 r = p0[i];
    #pragma unroll
    for (int j = 1; j < KSPLIT; j++) {
        float4 a = p0[i + j * 65536];
        r.x += a.x; r.y += a.y; r.z += a.z; r.w += a.w;
    }
    ((float4*)out)[i] = r;
}

// ---------------------------------------------------------------------------
extern "C" void kernel_launch(void* const* d_in, const int* in_sizes, int n_in,
                              void* d_out, int out_size) {
    const float* query = (const float*)d_in[0];
    const float* key   = (const float*)d_in[1];
    const float* value = (const float*)d_in[2];
    const int*   mask  = (const int*)d_in[3];
    const float* W1 = (const float*)d_in[4];
    const float* b1 = (const float*)d_in[5];
    const float* W2 = (const float*)d_in[6];
    const float* b2 = (const float*)d_in[7];
    const float* W3 = (const float*)d_in[8];
    const float* b3 = (const float*)d_in[9];

    float* out  = (float*)d_out;                 // [B, LQ, D]
    float* attn = out + (long)BB * LQ * DD;      // [B, LQ, LK]

    cudaFuncSetAttribute(proj_mma_kernel,
                         cudaFuncAttributeMaxDynamicSharedMemorySize, PM_SMEM);
    cudaFuncSetAttribute(score_mma_kernel,
                         cudaFuncAttributeMaxDynamicSharedMemorySize, SMEM_BYTES);

    w2bt_kernel<<<128, 256>>>(W2);
    proj_mma_kernel<<<dim3(LQ / 16, BB, 2), 512, PM_SMEM>>>(query, key, W1, b1);
    score_mma_kernel<<<SGRID, 512, SMEM_BYTES>>>(b2, W3, b3, attn);
    softmax_kernel<<<dim3(LQ / 8, BB), 256>>>(mask, attn);
    av_kernel<<<dim3(LQ / 8, KSPLIT, BB), 256>>>(value, attn);
    av_reduce_kernel<<<256, 256>>>(out);
}

// round 10
// speedup vs baseline: 1.9526x; 1.0034x over previous
#include <cuda_runtime.h>
#include <cuda_bf16.h>
#include <cstdint>

#define LQ 512
#define LK 512
#define DD 256
#define HH1 256
#define HH2 128
#define BB 2
#define KSPLIT 8
#define NTILES 2048      // 32 k-tiles * 32 q-tiles * 2 b
#define SGRID 148

// global scratch: projections [b][row][h_perm] (h contiguous, permuted within 16)
__device__ float g_qp[BB * LQ * HH1];
__device__ float g_kp[BB * LK * HH1];
// W2^T, bf16, [j=128][h_perm stride 272]
__device__ uint4 g_w2bt4[4352];
// AV partial sums [ks][b][q][d]
__device__ float g_av[KSPLIT * BB * LQ * DD];

// perm within 16-block: orig o -> pos ((o&6)<<1) + (o&1) + ((o&8)>>2)
__device__ __forceinline__ int hperm(int h) {
    int o = h & 15;
    return (h & ~15) + ((o & 6) << 1) + (o & 1) + ((o & 8) >> 2);
}

__device__ __forceinline__ uint32_t smem_addr(const void* p) {
    return (uint32_t)__cvta_generic_to_shared(p);
}
__device__ __forceinline__ void cp_async16(uint32_t saddr, const void* gaddr) {
    asm volatile("cp.async.cg.shared.global [%0], [%1], 16;" :: "r"(saddr), "l"(gaddr));
}
#define CP_COMMIT() asm volatile("cp.async.commit_group;" ::: "memory")
#define CP_WAIT1()  asm volatile("cp.async.wait_group 1;" ::: "memory")
#define CP_WAIT0()  asm volatile("cp.async.wait_group 0;" ::: "memory")

__device__ __forceinline__ void mma_tf32(float* c, const float* a, const float* b) {
    asm volatile(
        "mma.sync.aligned.m16n8k8.row.col.f32.tf32.tf32.f32 "
        "{%0,%1,%2,%3}, {%4,%5,%6,%7}, {%8,%9}, {%0,%1,%2,%3};"
        : "+f"(c[0]), "+f"(c[1]), "+f"(c[2]), "+f"(c[3])
        : "r"(__float_as_uint(a[0])), "r"(__float_as_uint(a[1])),
          "r"(__float_as_uint(a[2])), "r"(__float_as_uint(a[3])),
          "r"(__float_as_uint(b[0])), "r"(__float_as_uint(b[1])));
}

// ---------------------------------------------------------------------------
// Kernel 1: projections (z=0 query, z=1 key) via tf32 mma, cp.async-pipelined
// W1 chunks; z=2 slice packs W2^T bf16 (merged w2bt).
// ---------------------------------------------------------------------------
#define SXP 260
#define SWP 264
#define PM_SMEM ((16 * SXP + 2 * 64 * SWP) * 4)   // ~151.8 KB

__global__ void __launch_bounds__(512, 1)
proj_mma_kernel(const float* __restrict__ query,
                const float* __restrict__ key,
                const float* __restrict__ W1,
                const float* __restrict__ b1,
                const float* __restrict__ W2) {
    const int tid = threadIdx.x;

    if (blockIdx.z == 2) {   // merged w2bt: 64 blocks x 512 thr = 32768 elems
        int idx = (blockIdx.y * 32 + blockIdx.x) * 512 + tid;
        int j = idx & 127, h = idx >> 7;
        float v = __ldg(W2 + h * HH2 + j);
        __nv_bfloat16 bv = __float2bfloat16(v);
        ((uint16_t*)g_w2bt4)[j * 272 + hperm(h)] = *(uint16_t*)&bv;
        return;
    }

    extern __shared__ float psm[];
    float* sx = psm;                      // [16][SXP]
    float* sw1 = psm + 16 * SXP;          // [2][64][SWP]
    const uint32_t sw1a = smem_addr(sw1);

    const int row0 = blockIdx.x * 16;
    const int b = blockIdx.y;
    const int which = blockIdx.z;
    const float* W1h = W1 + (long)which * DD * HH1;

    // prefetch W1 chunk 0 (cp.async)
    #pragma unroll
    for (int i4 = tid; i4 < 4096; i4 += 512) {
        int dd = i4 >> 6, c = i4 & 63;
        cp_async16(sw1a + (uint32_t)(dd * SWP + c * 4) * 4, (const float4*)W1h + i4);
    }
    CP_COMMIT();

    // stage X tile [16][256]
    {
        const float4* X4 = (const float4*)((which ? key : query) + ((long)b * LQ + row0) * DD);
        #pragma unroll
        for (int i4 = tid; i4 < 1024; i4 += 512) {
            int r = i4 >> 6, c = i4 & 63;
            *(float4*)(sx + r * SXP + c * 4) = __ldg(X4 + i4);
        }
    }

    const int w = tid >> 5, lane = tid & 31;
    const int lr = lane >> 2, lc = lane & 3;
    const int n0 = w * 16;

    float acc[2][4];
    #pragma unroll
    for (int nt = 0; nt < 2; nt++)
        #pragma unroll
        for (int c = 0; c < 4; c++) acc[nt][c] = 0.f;

    #pragma unroll 1
    for (int dc = 0; dc < 4; dc++) {
        const int cur = dc & 1;
        if (dc + 1 < 4) {    // prefetch next chunk into other buffer
            const float4* src = (const float4*)(W1h + (long)(dc + 1) * 64 * HH1);
            const uint32_t dstb = sw1a + (uint32_t)((dc + 1) & 1) * (64 * SWP * 4);
            #pragma unroll
            for (int i4 = tid; i4 < 4096; i4 += 512) {
                int dd = i4 >> 6, c = i4 & 63;
                cp_async16(dstb + (uint32_t)(dd * SWP + c * 4) * 4, src + i4);
            }
            CP_COMMIT();
            CP_WAIT1();
        } else {
            CP_WAIT0();
        }
        __syncthreads();

        const float* sw = sw1 + cur * (64 * SWP);
        #pragma unroll
        for (int kc = 0; kc < 8; kc++) {
            const int kg = dc * 64 + kc * 8;
            const int kl = kc * 8;
            float a[4];
            a[0] = sx[lr * SXP + kg + lc];
            a[1] = sx[(lr + 8) * SXP + kg + lc];
            a[2] = sx[lr * SXP + kg + lc + 4];
            a[3] = sx[(lr + 8) * SXP + kg + lc + 4];
            #pragma unroll
            for (int nt = 0; nt < 2; nt++) {
                float bf[2];
                bf[0] = sw[(kl + lc) * SWP + n0 + nt * 8 + lr];
                bf[1] = sw[(kl + lc + 4) * SWP + n0 + nt * 8 + lr];
                mma_tf32(acc[nt], a, bf);
            }
        }
        __syncthreads();   // protect buffer reuse by next prefetch
    }

    float* dstb = (which ? g_kp : g_qp) + ((long)b * LQ + row0) * HH1;
    #pragma unroll
    for (int nt = 0; nt < 2; nt++) {
        const int n = n0 + nt * 8 + 2 * lc;
        const float bb0 = which ? 0.f : __ldg(b1 + n);
        const float bb1 = which ? 0.f : __ldg(b1 + n + 1);
        const int hp0 = hperm(n), hp1 = hperm(n + 1);
        dstb[(long)lr * HH1 + hp0]       = acc[nt][0] + bb0;
        dstb[(long)lr * HH1 + hp1]       = acc[nt][1] + bb1;
        dstb[(long)(lr + 8) * HH1 + hp0] = acc[nt][2] + bb0;
        dstb[(long)(lr + 8) * HH1 + hp1] = acc[nt][3] + bb1;
    }
}

// ---------------------------------------------------------------------------
// Kernel 2: PERSISTENT fused MLP score kernel (mma.sync m16n8k16 bf16).
// ---------------------------------------------------------------------------
#define OFF_W2B   0                    // bf16 [128][272] = 69632 B
#define OFF_QP0   69632                // fp32 [16][272] = 17408 B
#define OFF_KP0   87040
#define OFF_QP1   104448
#define OFF_KP1   121856
#define OFF_BWB   139264               // float2[128] = 1024 B
#define OFF_PARTB 140288               // float[512] = 2048 B
#define SMEM_BYTES 142336

__device__ __forceinline__ uint32_t pack_relu_bf16(float lo, float hi) {
    uint32_t r;
    asm("cvt.rn.bf16x2.f32 %0, %1, %2;" : "=r"(r) : "f"(hi), "f"(lo));
    asm("max.bf16x2 %0, %0, %1;" : "+r"(r) : "r"(0u));
    return r;
}

__device__ __forceinline__ void mma_bf16(float* c, const uint32_t* a, const uint32_t* b) {
    asm volatile(
        "mma.sync.aligned.m16n8k16.row.col.f32.bf16.bf16.f32 "
        "{%0,%1,%2,%3}, {%4,%5,%6,%7}, {%8,%9}, {%0,%1,%2,%3};"
        : "+f"(c[0]), "+f"(c[1]), "+f"(c[2]), "+f"(c[3])
        : "r"(a[0]), "r"(a[1]), "r"(a[2]), "r"(a[3]), "r"(b[0]), "r"(b[1]));
}

__global__ void __launch_bounds__(512, 1)
score_mma_kernel(const float* __restrict__ b2, const float* __restrict__ W3,
                 const float* __restrict__ b3, float* __restrict__ scores) {
    extern __shared__ char smem[];
    float* smemf = (float*)smem;
    const int tid = threadIdx.x;
    const uint32_t sbase = smem_addr(smem);

    // prefetch first tile's qp/kp
    {
        const int t0 = blockIdx.x;
        const int kb = t0 & 31, qb = (t0 >> 5) & 31, b = t0 >> 10;
        const float4* gq = (const float4*)(g_qp + ((long)b * LQ + qb * 16) * HH1);
        const float4* gk = (const float4*)(g_kp + ((long)b * LK + kb * 16) * HH1);
        #pragma unroll
        for (int i4 = tid; i4 < 1024; i4 += 512) {
            int r = i4 >> 6, c = i4 & 63;
            uint32_t off = (uint32_t)(r * 68 + c) * 16;
            cp_async16(sbase + OFF_QP0 + off, gq + i4);
            cp_async16(sbase + OFF_KP0 + off, gk + i4);
        }
        CP_COMMIT();
    }

    // stage W2 + b2/W3 once
    {
        uint4* dW = (uint4*)(smem + OFF_W2B);
        #pragma unroll 4
        for (int i = tid; i < 4352; i += 512) dW[i] = g_w2bt4[i];
        if (tid < HH2)
            ((float2*)(smem + OFF_BWB))[tid] = make_float2(__ldg(b2 + tid), __ldg(W3 + tid));
    }

    const int w = tid >> 5, lane = tid & 31;
    const int mwarp = w & 7;
    const int nwarp = w >> 3;
    const int n0 = nwarp * 64;
    const int lr = lane >> 2, lc = lane & 3;
    const uint16_t* w2p = (const uint16_t*)(smem + OFF_W2B) + (n0 + lr) * 272 + 4 * lc;
    const float2* bw = (const float2*)(smem + OFF_BWB);
    float* part = smemf + OFF_PARTB / 4;
    const float bb3 = __ldg(b3);

    int it = 0;
    #pragma unroll 1
    for (int t = blockIdx.x; t < NTILES; t += SGRID, it++) {
        const int cur = it & 1;
        const int qoff = cur ? OFF_QP1 : OFF_QP0;
        const int koff = cur ? OFF_KP1 : OFF_KP0;

        const int t2 = t + SGRID;
        if (t2 < NTILES) {
            const int kb2 = t2 & 31, qb2 = (t2 >> 5) & 31, b2i = t2 >> 10;
            const float4* gq = (const float4*)(g_qp + ((long)b2i * LQ + qb2 * 16) * HH1);
            const float4* gk = (const float4*)(g_kp + ((long)b2i * LK + kb2 * 16) * HH1);
            const int qo2 = cur ? OFF_QP0 : OFF_QP1;
            const int ko2 = cur ? OFF_KP0 : OFF_KP1;
            #pragma unroll
            for (int i4 = tid; i4 < 1024; i4 += 512) {
                int r = i4 >> 6, c = i4 & 63;
                uint32_t off = (uint32_t)(r * 68 + c) * 16;
                cp_async16(sbase + qo2 + off, gq + i4);
                cp_async16(sbase + ko2 + off, gk + i4);
            }
            CP_COMMIT();
            CP_WAIT1();
        } else {
            CP_WAIT0();
        }
        __syncthreads();

        const int kb = t & 31, qb = (t >> 5) & 31, b = t >> 10;

        float acc[2][8][4];
        #pragma unroll
        for (int mt = 0; mt < 2; mt++)
            #pragma unroll
            for (int nt = 0; nt < 8; nt++)
                #pragma unroll
                for (int c = 0; c < 4; c++) acc[mt][nt][c] = 0.f;

        const float* kpA = smemf + koff / 4 + lr * 272 + 4 * lc;
        const float* kpB = kpA + 8 * 272;
        const float* qpb = smemf + qoff / 4 + (mwarp * 2) * 272 + 4 * lc;

        #pragma unroll 4
        for (int c = 0; c < 16; c++) {
            const int hb = c * 16;
            const float4 kA = *(const float4*)(kpA + hb);
            const float4 kB = *(const float4*)(kpB + hb);
            uint2 bfr[8];
            #pragma unroll
            for (int nt = 0; nt < 8; nt++)
                bfr[nt] = *(const uint2*)(w2p + nt * (8 * 272) + hb);

            #pragma unroll
            for (int mt = 0; mt < 2; mt++) {
                const float4 q4 = *(const float4*)(qpb + mt * 272 + hb);
                uint32_t a[4];
                a[0] = pack_relu_bf16(q4.x + kA.x, q4.y + kA.y);
                a[1] = pack_relu_bf16(q4.x + kB.x, q4.y + kB.y);
                a[2] = pack_relu_bf16(q4.z + kA.z, q4.w + kA.w);
                a[3] = pack_relu_bf16(q4.z + kB.z, q4.w + kB.w);
                #pragma unroll
                for (int nt = 0; nt < 8; nt++)
                    mma_bf16(acc[mt][nt], a, (const uint32_t*)&bfr[nt]);
            }
        }

        float s0[2], s1[2];
        #pragma unroll
        for (int mt = 0; mt < 2; mt++) {
            float t0 = 0.f, t1 = 0.f;
            #pragma unroll
            for (int nt = 0; nt < 8; nt++) {
                const int jj = n0 + nt * 8 + 2 * lc;
                float2 cA = bw[jj];
                float2 cB = bw[jj + 1];
                t0 = fmaf(fmaxf(acc[mt][nt][0] + cA.x, 0.f), cA.y, t0);
                t0 = fmaf(fmaxf(acc[mt][nt][1] + cB.x, 0.f), cB.y, t0);
                t1 = fmaf(fmaxf(acc[mt][nt][2] + cA.x, 0.f), cA.y, t1);
                t1 = fmaf(fmaxf(acc[mt][nt][3] + cB.x, 0.f), cB.y, t1);
            }
            s0[mt] = t0; s1[mt] = t1;
        }
        #pragma unroll
        for (int off = 1; off < 4; off <<= 1)
            #pragma unroll
            for (int mt = 0; mt < 2; mt++) {
                s0[mt] += __shfl_xor_sync(0xffffffffu, s0[mt], off);
                s1[mt] += __shfl_xor_sync(0xffffffffu, s1[mt], off);
            }

        if (lc == 0) {
            #pragma unroll
            for (int mt = 0; mt < 2; mt++) {
                part[nwarp * 256 + (mwarp * 2 + mt) * 16 + lr]     = s0[mt];
                part[nwarp * 256 + (mwarp * 2 + mt) * 16 + lr + 8] = s1[mt];
            }
        }
        __syncthreads();
        if (tid < 256) {
            const int p = tid;
            float f = part[p] + part[256 + p] + bb3;
            const int q = qb * 16 + (p >> 4);
            scores[((long)b * LQ + q) * LK + kb * 16 + (p & 15)] = f;
        }
    }
}

// ---------------------------------------------------------------------------
// Kernel 3: mask + softmax over k (warp-per-row), writes attn in place.
// ---------------------------------------------------------------------------
__global__ void __launch_bounds__(256, 2)
softmax_kernel(const int* __restrict__ mask, float* __restrict__ attn) {
    const int b = blockIdx.y;
    const int q0 = blockIdx.x * 8;
    const int tid = threadIdx.x;
    const int w = tid >> 5, lane = tid & 31;

    const long rowbase = ((long)b * LQ + q0 + w) * LK;
    float vals[16];
    float mx = -3.4e38f;
    #pragma unroll
    for (int i = 0; i < 16; i++) {
        int k = lane + i * 32;
        float s = attn[rowbase + k];
        if (__ldg(mask + rowbase + k) == 0) s = -1e9f;
        vals[i] = s;
        mx = fmaxf(mx, s);
    }
    #pragma unroll
    for (int off = 16; off > 0; off >>= 1)
        mx = fmaxf(mx, __shfl_xor_sync(0xffffffffu, mx, off));

    float sum = 0.f;
    #pragma unroll
    for (int i = 0; i < 16; i++) {
        vals[i] = __expf(vals[i] - mx);
        sum += vals[i];
    }
    #pragma unroll
    for (int off = 16; off > 0; off >>= 1)
        sum += __shfl_xor_sync(0xffffffffu, sum, off);
    const float inv = 1.f / sum;

    #pragma unroll
    for (int i = 0; i < 16; i++)
        attn[rowbase + lane + i * 32] = vals[i] * inv;
}

// ---------------------------------------------------------------------------
// Kernel 4: AV partials, float4 V loads.  Block = (8 q, 64-k split, b).
// thread: d-group = (tid&63)*4, row pair = tid>>6 -> rows {rp*2, rp*2+1}
// ---------------------------------------------------------------------------
__global__ void __launch_bounds__(256, 4)
av_kernel(const float* __restrict__ value, const float* __restrict__ attn) {
    __shared__ float sa[8][64];
    const int q0 = blockIdx.x * 8;
    const int ks = blockIdx.y;
    const int b = blockIdx.z;
    const int tid = threadIdx.x;

    #pragma unroll
    for (int i = tid; i < 512; i += 256) {
        int r = i >> 6, k = i & 63;
        sa[r][k] = attn[((long)b * LQ + q0 + r) * LK + ks * 64 + k];
    }
    __syncthreads();

    const int dg = tid & 63;          // d = dg*4
    const int rp = tid >> 6;          // rows rp*2, rp*2+1
    float4 acc0 = make_float4(0.f, 0.f, 0.f, 0.f);
    float4 acc1 = make_float4(0.f, 0.f, 0.f, 0.f);
    const float4* Vb = (const float4*)(value + ((long)b * LK + ks * 64) * DD) + dg;

    #pragma unroll 8
    for (int k = 0; k < 64; k++) {
        float4 v = __ldg(Vb + (long)k * (DD / 4));
        float a0 = sa[rp * 2][k], a1 = sa[rp * 2 + 1][k];
        acc0.x = fmaf(a0, v.x, acc0.x); acc0.y = fmaf(a0, v.y, acc0.y);
        acc0.z = fmaf(a0, v.z, acc0.z); acc0.w = fmaf(a0, v.w, acc0.w);
        acc1.x = fmaf(a1, v.x, acc1.x); acc1.y = fmaf(a1, v.y, acc1.y);
        acc1.z = fmaf(a1, v.z, acc1.z); acc1.w = fmaf(a1, v.w, acc1.w);
    }

    float4* dst = (float4*)(g_av + (long)ks * (BB * LQ * DD) + ((long)b * LQ + q0) * DD) + dg;
    dst[(long)(rp * 2) * (DD / 4)]     = acc0;
    dst[(long)(rp * 2 + 1) * (DD / 4)] = acc1;
}

// ---------------------------------------------------------------------------
// Kernel 5: reduce the KSPLIT partials into out.
// ---------------------------------------------------------------------------
__global__ void __launch_bounds__(256, 4)
av_reduce_kernel(float* __restrict__ out) {
    const int i = blockIdx.x * 256 + threadIdx.x;     // float4 index
    const float4* p0 = (const float4*)g_av;
    float4 r = p0[i];
    #pragma unroll
    for (int j = 1; j < KSPLIT; j++) {
        float4 a = p0[i + j * 65536];
        r.x += a.x; r.y += a.y; r.z += a.z; r.w += a.w;
    }
    ((float4*)out)[i] = r;
}

// ---------------------------------------------------------------------------
extern "C" void kernel_launch(void* const* d_in, const int* in_sizes, int n_in,
                              void* d_out, int out_size) {
    const float* query = (const float*)d_in[0];
    const float* key   = (const float*)d_in[1];
    const float* value = (const float*)d_in[2];
    const int*   mask  = (const int*)d_in[3];
    const float* W1 = (const float*)d_in[4];
    const float* b1 = (const float*)d_in[5];
    const float* W2 = (const float*)d_in[6];
    const float* b2 = (const float*)d_in[7];
    const float* W3 = (const float*)d_in[8];
    const float* b3 = (const float*)d_in[9];

    float* out  = (float*)d_out;                 // [B, LQ, D]
    float* attn = out + (long)BB * LQ * DD;      // [B, LQ, LK]

    cudaFuncSetAttribute(proj_mma_kernel,
                         cudaFuncAttributeMaxDynamicSharedMemorySize, PM_SMEM);
    cudaFuncSetAttribute(score_mma_kernel,
                         cudaFuncAttributeMaxDynamicSharedMemorySize, SMEM_BYTES);

    proj_mma_kernel<<<dim3(LQ / 16, BB, 3), 512, PM_SMEM>>>(query, key, W1, b1, W2);
    score_mma_kernel<<<SGRID, 512, SMEM_BYTES>>>(b2, W3, b3, attn);
    softmax_kernel<<<dim3(LQ / 8, BB), 256>>>(mask, attn);
    av_kernel<<<dim3(LQ / 8, KSPLIT, BB), 256>>>(value, attn);
    av_reduce_kernel<<<256, 256>>>(out);
}

// round 11
// speedup vs baseline: 2.1361x; 1.0939x over previous
#include <cuda_runtime.h>
#include <cuda_bf16.h>
#include <cstdint>

#define LQ 512
#define LK 512
#define DD 256
#define HH1 256
#define HH2 128
#define BB 2
#define NTILES 2048      // 32 k-tiles * 32 q-tiles * 2 b
#define SGRID 148

// global scratch: projections [b][row][h_perm] (h contiguous, permuted within 16)
__device__ float g_qp[BB * LQ * HH1];
__device__ float g_kp[BB * LK * HH1];
// W2^T, bf16, [j=128][h_perm stride 272]
__device__ uint4 g_w2bt4[4352];

// perm within 16-block: orig o -> pos ((o&6)<<1) + (o&1) + ((o&8)>>2)
__device__ __forceinline__ int hperm(int h) {
    int o = h & 15;
    return (h & ~15) + ((o & 6) << 1) + (o & 1) + ((o & 8) >> 2);
}

__device__ __forceinline__ uint32_t smem_addr(const void* p) {
    return (uint32_t)__cvta_generic_to_shared(p);
}
__device__ __forceinline__ void cp_async16(uint32_t saddr, const void* gaddr) {
    asm volatile("cp.async.cg.shared.global [%0], [%1], 16;" :: "r"(saddr), "l"(gaddr));
}
#define CP_COMMIT() asm volatile("cp.async.commit_group;" ::: "memory")
#define CP_WAIT1()  asm volatile("cp.async.wait_group 1;" ::: "memory")
#define CP_WAIT0()  asm volatile("cp.async.wait_group 0;" ::: "memory")

__device__ __forceinline__ void mma_tf32(float* c, const float* a, const float* b) {
    asm volatile(
        "mma.sync.aligned.m16n8k8.row.col.f32.tf32.tf32.f32 "
        "{%0,%1,%2,%3}, {%4,%5,%6,%7}, {%8,%9}, {%0,%1,%2,%3};"
        : "+f"(c[0]), "+f"(c[1]), "+f"(c[2]), "+f"(c[3])
        : "r"(__float_as_uint(a[0])), "r"(__float_as_uint(a[1])),
          "r"(__float_as_uint(a[2])), "r"(__float_as_uint(a[3])),
          "r"(__float_as_uint(b[0])), "r"(__float_as_uint(b[1])));
}

// ---------------------------------------------------------------------------
// Kernel 1: projections (z=0 query, z=1 key) via tf32 mma, cp.async-pipelined
// W1 chunks; z=2 slice packs W2^T bf16.
// ---------------------------------------------------------------------------
#define SXP 260
#define SWP 264
#define PM_SMEM ((16 * SXP + 2 * 64 * SWP) * 4)   // ~151.8 KB

__global__ void __launch_bounds__(512, 1)
proj_mma_kernel(const float* __restrict__ query,
                const float* __restrict__ key,
                const float* __restrict__ W1,
                const float* __restrict__ b1,
                const float* __restrict__ W2) {
    const int tid = threadIdx.x;

    if (blockIdx.z == 2) {   // merged w2bt: 64 blocks x 512 thr = 32768 elems
        int idx = (blockIdx.y * 32 + blockIdx.x) * 512 + tid;
        int j = idx & 127, h = idx >> 7;
        float v = __ldg(W2 + h * HH2 + j);
        __nv_bfloat16 bv = __float2bfloat16(v);
        ((uint16_t*)g_w2bt4)[j * 272 + hperm(h)] = *(uint16_t*)&bv;
        return;
    }

    extern __shared__ float psm[];
    float* sx = psm;                      // [16][SXP]
    float* sw1 = psm + 16 * SXP;          // [2][64][SWP]
    const uint32_t sw1a = smem_addr(sw1);

    const int row0 = blockIdx.x * 16;
    const int b = blockIdx.y;
    const int which = blockIdx.z;
    const float* W1h = W1 + (long)which * DD * HH1;

    #pragma unroll
    for (int i4 = tid; i4 < 4096; i4 += 512) {
        int dd = i4 >> 6, c = i4 & 63;
        cp_async16(sw1a + (uint32_t)(dd * SWP + c * 4) * 4, (const float4*)W1h + i4);
    }
    CP_COMMIT();

    {
        const float4* X4 = (const float4*)((which ? key : query) + ((long)b * LQ + row0) * DD);
        #pragma unroll
        for (int i4 = tid; i4 < 1024; i4 += 512) {
            int r = i4 >> 6, c = i4 & 63;
            *(float4*)(sx + r * SXP + c * 4) = __ldg(X4 + i4);
        }
    }

    const int w = tid >> 5, lane = tid & 31;
    const int lr = lane >> 2, lc = lane & 3;
    const int n0 = w * 16;

    float acc[2][4];
    #pragma unroll
    for (int nt = 0; nt < 2; nt++)
        #pragma unroll
        for (int c = 0; c < 4; c++) acc[nt][c] = 0.f;

    #pragma unroll 1
    for (int dc = 0; dc < 4; dc++) {
        const int cur = dc & 1;
        if (dc + 1 < 4) {
            const float4* src = (const float4*)(W1h + (long)(dc + 1) * 64 * HH1);
            const uint32_t dstb = sw1a + (uint32_t)((dc + 1) & 1) * (64 * SWP * 4);
            #pragma unroll
            for (int i4 = tid; i4 < 4096; i4 += 512) {
                int dd = i4 >> 6, c = i4 & 63;
                cp_async16(dstb + (uint32_t)(dd * SWP + c * 4) * 4, src + i4);
            }
            CP_COMMIT();
            CP_WAIT1();
        } else {
            CP_WAIT0();
        }
        __syncthreads();

        const float* sw = sw1 + cur * (64 * SWP);
        #pragma unroll
        for (int kc = 0; kc < 8; kc++) {
            const int kg = dc * 64 + kc * 8;
            const int kl = kc * 8;
            float a[4];
            a[0] = sx[lr * SXP + kg + lc];
            a[1] = sx[(lr + 8) * SXP + kg + lc];
            a[2] = sx[lr * SXP + kg + lc + 4];
            a[3] = sx[(lr + 8) * SXP + kg + lc + 4];
            #pragma unroll
            for (int nt = 0; nt < 2; nt++) {
                float bf[2];
                bf[0] = sw[(kl + lc) * SWP + n0 + nt * 8 + lr];
                bf[1] = sw[(kl + lc + 4) * SWP + n0 + nt * 8 + lr];
                mma_tf32(acc[nt], a, bf);
            }
        }
        __syncthreads();
    }

    float* dstb = (which ? g_kp : g_qp) + ((long)b * LQ + row0) * HH1;
    #pragma unroll
    for (int nt = 0; nt < 2; nt++) {
        const int n = n0 + nt * 8 + 2 * lc;
        const float bb0 = which ? 0.f : __ldg(b1 + n);
        const float bb1 = which ? 0.f : __ldg(b1 + n + 1);
        const int hp0 = hperm(n), hp1 = hperm(n + 1);
        dstb[(long)lr * HH1 + hp0]       = acc[nt][0] + bb0;
        dstb[(long)lr * HH1 + hp1]       = acc[nt][1] + bb1;
        dstb[(long)(lr + 8) * HH1 + hp0] = acc[nt][2] + bb0;
        dstb[(long)(lr + 8) * HH1 + hp1] = acc[nt][3] + bb1;
    }
}

// ---------------------------------------------------------------------------
// Kernel 2: PERSISTENT fused MLP score kernel (mma.sync m16n8k16 bf16).
// ---------------------------------------------------------------------------
#define OFF_W2B   0                    // bf16 [128][272] = 69632 B
#define OFF_QP0   69632                // fp32 [16][272] = 17408 B
#define OFF_KP0   87040
#define OFF_QP1   104448
#define OFF_KP1   121856
#define OFF_BWB   139264               // float2[128] = 1024 B
#define OFF_PARTB 140288               // float[512] = 2048 B
#define SMEM_BYTES 142336

__device__ __forceinline__ uint32_t pack_relu_bf16(float lo, float hi) {
    uint32_t r;
    asm("cvt.rn.bf16x2.f32 %0, %1, %2;" : "=r"(r) : "f"(hi), "f"(lo));
    asm("max.bf16x2 %0, %0, %1;" : "+r"(r) : "r"(0u));
    return r;
}

__device__ __forceinline__ void mma_bf16(float* c, const uint32_t* a, const uint32_t* b) {
    asm volatile(
        "mma.sync.aligned.m16n8k16.row.col.f32.bf16.bf16.f32 "
        "{%0,%1,%2,%3}, {%4,%5,%6,%7}, {%8,%9}, {%0,%1,%2,%3};"
        : "+f"(c[0]), "+f"(c[1]), "+f"(c[2]), "+f"(c[3])
        : "r"(a[0]), "r"(a[1]), "r"(a[2]), "r"(a[3]), "r"(b[0]), "r"(b[1]));
}

__global__ void __launch_bounds__(512, 1)
score_mma_kernel(const float* __restrict__ b2, const float* __restrict__ W3,
                 const float* __restrict__ b3, float* __restrict__ scores) {
    extern __shared__ char smem[];
    float* smemf = (float*)smem;
    const int tid = threadIdx.x;
    const uint32_t sbase = smem_addr(smem);

    {
        const int t0 = blockIdx.x;
        const int kb = t0 & 31, qb = (t0 >> 5) & 31, b = t0 >> 10;
        const float4* gq = (const float4*)(g_qp + ((long)b * LQ + qb * 16) * HH1);
        const float4* gk = (const float4*)(g_kp + ((long)b * LK + kb * 16) * HH1);
        #pragma unroll
        for (int i4 = tid; i4 < 1024; i4 += 512) {
            int r = i4 >> 6, c = i4 & 63;
            uint32_t off = (uint32_t)(r * 68 + c) * 16;
            cp_async16(sbase + OFF_QP0 + off, gq + i4);
            cp_async16(sbase + OFF_KP0 + off, gk + i4);
        }
        CP_COMMIT();
    }

    {
        uint4* dW = (uint4*)(smem + OFF_W2B);
        #pragma unroll 4
        for (int i = tid; i < 4352; i += 512) dW[i] = g_w2bt4[i];
        if (tid < HH2)
            ((float2*)(smem + OFF_BWB))[tid] = make_float2(__ldg(b2 + tid), __ldg(W3 + tid));
    }

    const int w = tid >> 5, lane = tid & 31;
    const int mwarp = w & 7;
    const int nwarp = w >> 3;
    const int n0 = nwarp * 64;
    const int lr = lane >> 2, lc = lane & 3;
    const uint16_t* w2p = (const uint16_t*)(smem + OFF_W2B) + (n0 + lr) * 272 + 4 * lc;
    const float2* bw = (const float2*)(smem + OFF_BWB);
    float* part = smemf + OFF_PARTB / 4;
    const float bb3 = __ldg(b3);

    int it = 0;
    #pragma unroll 1
    for (int t = blockIdx.x; t < NTILES; t += SGRID, it++) {
        const int cur = it & 1;
        const int qoff = cur ? OFF_QP1 : OFF_QP0;
        const int koff = cur ? OFF_KP1 : OFF_KP0;

        const int t2 = t + SGRID;
        if (t2 < NTILES) {
            const int kb2 = t2 & 31, qb2 = (t2 >> 5) & 31, b2i = t2 >> 10;
            const float4* gq = (const float4*)(g_qp + ((long)b2i * LQ + qb2 * 16) * HH1);
            const float4* gk = (const float4*)(g_kp + ((long)b2i * LK + kb2 * 16) * HH1);
            const int qo2 = cur ? OFF_QP0 : OFF_QP1;
            const int ko2 = cur ? OFF_KP0 : OFF_KP1;
            #pragma unroll
            for (int i4 = tid; i4 < 1024; i4 += 512) {
                int r = i4 >> 6, c = i4 & 63;
                uint32_t off = (uint32_t)(r * 68 + c) * 16;
                cp_async16(sbase + qo2 + off, gq + i4);
                cp_async16(sbase + ko2 + off, gk + i4);
            }
            CP_COMMIT();
            CP_WAIT1();
        } else {
            CP_WAIT0();
        }
        __syncthreads();

        const int kb = t & 31, qb = (t >> 5) & 31, b = t >> 10;

        float acc[2][8][4];
        #pragma unroll
        for (int mt = 0; mt < 2; mt++)
            #pragma unroll
            for (int nt = 0; nt < 8; nt++)
                #pragma unroll
                for (int c = 0; c < 4; c++) acc[mt][nt][c] = 0.f;

        const float* kpA = smemf + koff / 4 + lr * 272 + 4 * lc;
        const float* kpB = kpA + 8 * 272;
        const float* qpb = smemf + qoff / 4 + (mwarp * 2) * 272 + 4 * lc;

        #pragma unroll 4
        for (int c = 0; c < 16; c++) {
            const int hb = c * 16;
            const float4 kA = *(const float4*)(kpA + hb);
            const float4 kB = *(const float4*)(kpB + hb);
            uint2 bfr[8];
            #pragma unroll
            for (int nt = 0; nt < 8; nt++)
                bfr[nt] = *(const uint2*)(w2p + nt * (8 * 272) + hb);

            #pragma unroll
            for (int mt = 0; mt < 2; mt++) {
                const float4 q4 = *(const float4*)(qpb + mt * 272 + hb);
                uint32_t a[4];
                a[0] = pack_relu_bf16(q4.x + kA.x, q4.y + kA.y);
                a[1] = pack_relu_bf16(q4.x + kB.x, q4.y + kB.y);
                a[2] = pack_relu_bf16(q4.z + kA.z, q4.w + kA.w);
                a[3] = pack_relu_bf16(q4.z + kB.z, q4.w + kB.w);
                #pragma unroll
                for (int nt = 0; nt < 8; nt++)
                    mma_bf16(acc[mt][nt], a, (const uint32_t*)&bfr[nt]);
            }
        }

        float s0[2], s1[2];
        #pragma unroll
        for (int mt = 0; mt < 2; mt++) {
            float t0 = 0.f, t1 = 0.f;
            #pragma unroll
            for (int nt = 0; nt < 8; nt++) {
                const int jj = n0 + nt * 8 + 2 * lc;
                float2 cA = bw[jj];
                float2 cB = bw[jj + 1];
                t0 = fmaf(fmaxf(acc[mt][nt][0] + cA.x, 0.f), cA.y, t0);
                t0 = fmaf(fmaxf(acc[mt][nt][1] + cB.x, 0.f), cB.y, t0);
                t1 = fmaf(fmaxf(acc[mt][nt][2] + cA.x, 0.f), cA.y, t1);
                t1 = fmaf(fmaxf(acc[mt][nt][3] + cB.x, 0.f), cB.y, t1);
            }
            s0[mt] = t0; s1[mt] = t1;
        }
        #pragma unroll
        for (int off = 1; off < 4; off <<= 1)
            #pragma unroll
            for (int mt = 0; mt < 2; mt++) {
                s0[mt] += __shfl_xor_sync(0xffffffffu, s0[mt], off);
                s1[mt] += __shfl_xor_sync(0xffffffffu, s1[mt], off);
            }

        if (lc == 0) {
            #pragma unroll
            for (int mt = 0; mt < 2; mt++) {
                part[nwarp * 256 + (mwarp * 2 + mt) * 16 + lr]     = s0[mt];
                part[nwarp * 256 + (mwarp * 2 + mt) * 16 + lr + 8] = s1[mt];
            }
        }
        __syncthreads();
        if (tid < 256) {
            const int p = tid;
            float f = part[p] + part[256 + p] + bb3;
            const int q = qb * 16 + (p >> 4);
            scores[((long)b * LQ + q) * LK + kb * 16 + (p & 15)] = f;
        }
    }
}

// ---------------------------------------------------------------------------
// Kernel 3: FUSED softmax + AV (tf32 mma).
// Block = (16 q rows, 128-d half, b).  256 threads / 8 warps.
// Phase 1: warp-per-row masked softmax -> attn global (dh==0) + smem sa.
// Phase 2: out[16,128] = attn[16,512] @ V[512,128] via m16n8k8 tf32,
//          V streamed in 64-k chunks, triple-buffered cp.async.
// ---------------------------------------------------------------------------
#define SA_STR 516                      // attn smem stride (floats): banks 4lr+lc
#define SV_STR 136                      // V smem stride (floats): banks 8lc+lr
#define FOFF_SA 0                       // [16][516] = 33024 floats? bytes: 33024B
#define FOFF_V  (16 * SA_STR)           // 3 x [64][136]
#define F_SMEM_FLOATS (16 * SA_STR + 3 * 64 * SV_STR)
#define F_SMEM_BYTES (F_SMEM_FLOATS * 4)   // 137600 B

__global__ void __launch_bounds__(256, 1)
fused_softmax_av_kernel(const float* __restrict__ value,
                        const int* __restrict__ mask,
                        float* __restrict__ out,
                        float* __restrict__ attn) {
    extern __shared__ float fsm[];
    float* sa = fsm;                    // [16][SA_STR]
    float* sv = fsm + FOFF_V;           // [3][64][SV_STR]
    const uint32_t sva = smem_addr(sv);

    const int tid = threadIdx.x;
    const int w = tid >> 5, lane = tid & 31;
    const int qt = blockIdx.x;          // 16-row tile
    const int dh = blockIdx.y;          // d half
    const int b = blockIdx.z;
    const int q0 = qt * 16;

    const float* Vb = value + (long)b * LK * DD + dh * 128;

    // pre-issue V chunks 0,1 (each: 64 k-rows x 128 floats)
    #pragma unroll
    for (int cpre = 0; cpre < 2; cpre++) {
        const float4* src = (const float4*)(Vb);
        #pragma unroll
        for (int i4 = tid; i4 < 2048; i4 += 256) {
            int r = i4 >> 5, cc = i4 & 31;
            cp_async16(sva + (uint32_t)(cpre * 64 * SV_STR + r * SV_STR + cc * 4) * 4,
                       (const float4*)(Vb + (long)(cpre * 64 + r) * DD) + cc);
        }
        (void)src;
        CP_COMMIT();
    }

    // ---- phase 1: softmax, 2 rows per warp ----
    #pragma unroll
    for (int rr = 0; rr < 2; rr++) {
        const int r = w * 2 + rr;
        const long rowbase = ((long)b * LQ + q0 + r) * LK;
        float vals[16];
        float mx = -3.4e38f;
        #pragma unroll
        for (int i = 0; i < 16; i++) {
            int k = lane + i * 32;
            float s = attn[rowbase + k];
            if (__ldg(mask + rowbase + k) == 0) s = -1e9f;
            vals[i] = s;
            mx = fmaxf(mx, s);
        }
        #pragma unroll
        for (int off = 16; off > 0; off >>= 1)
            mx = fmaxf(mx, __shfl_xor_sync(0xffffffffu, mx, off));

        float sum = 0.f;
        #pragma unroll
        for (int i = 0; i < 16; i++) {
            vals[i] = __expf(vals[i] - mx);
            sum += vals[i];
        }
        #pragma unroll
        for (int off = 16; off > 0; off >>= 1)
            sum += __shfl_xor_sync(0xffffffffu, sum, off);
        const float inv = 1.f / sum;

        #pragma unroll
        for (int i = 0; i < 16; i++) {
            const int k = lane + i * 32;
            const float a = vals[i] * inv;
            sa[r * SA_STR + k] = a;
            if (dh == 0) attn[rowbase + k] = a;
        }
    }

    // ---- phase 2: mma AV ----
    const int lr = lane >> 2, lc = lane & 3;
    const int n0 = w * 16;              // warp n-slice within 128

    float acc[2][4];
    #pragma unroll
    for (int nt = 0; nt < 2; nt++)
        #pragma unroll
        for (int c = 0; c < 4; c++) acc[nt][c] = 0.f;

    #pragma unroll 1
    for (int c = 0; c < 8; c++) {
        if (c < 7) { CP_WAIT1(); } else { CP_WAIT0(); }
        __syncthreads();

        // prefetch chunk c+2 into buffer (c+2)%3 (safe: all warps past chunk c-1)
        if (c + 2 < 8) {
            const int buf = (c + 2) % 3;
            #pragma unroll
            for (int i4 = tid; i4 < 2048; i4 += 256) {
                int r = i4 >> 5, cc = i4 & 31;
                cp_async16(sva + (uint32_t)(buf * 64 * SV_STR + r * SV_STR + cc * 4) * 4,
                           (const float4*)(Vb + (long)((c + 2) * 64 + r) * DD) + cc);
            }
            CP_COMMIT();
        }

        const float* svc = sv + (c % 3) * (64 * SV_STR);
        const int kg = c * 64;
        #pragma unroll
        for (int ks = 0; ks < 8; ks++) {
            const int k0 = ks * 8;
            float a[4];
            a[0] = sa[lr * SA_STR + kg + k0 + lc];
            a[1] = sa[(lr + 8) * SA_STR + kg + k0 + lc];
            a[2] = sa[lr * SA_STR + kg + k0 + lc + 4];
            a[3] = sa[(lr + 8) * SA_STR + kg + k0 + lc + 4];
            #pragma unroll
            for (int nt = 0; nt < 2; nt++) {
                float bf[2];
                bf[0] = svc[(k0 + lc) * SV_STR + n0 + nt * 8 + lr];
                bf[1] = svc[(k0 + lc + 4) * SV_STR + n0 + nt * 8 + lr];
                mma_tf32(acc[nt], a, bf);
            }
        }
    }

    // epilogue: write out rows lr/lr+8, cols dh*128 + n0 + nt*8 + 2lc (+1)
    #pragma unroll
    for (int nt = 0; nt < 2; nt++) {
        const int col = dh * 128 + n0 + nt * 8 + 2 * lc;
        float* o0 = out + ((long)b * LQ + q0 + lr) * DD + col;
        float* o1 = out + ((long)b * LQ + q0 + lr + 8) * DD + col;
        *(float2*)o0 = make_float2(acc[nt][0], acc[nt][1]);
        *(float2*)o1 = make_float2(acc[nt][2], acc[nt][3]);
    }
}

// ---------------------------------------------------------------------------
extern "C" void kernel_launch(void* const* d_in, const int* in_sizes, int n_in,
                              void* d_out, int out_size) {
    const float* query = (const float*)d_in[0];
    const float* key   = (const float*)d_in[1];
    const float* value = (const float*)d_in[2];
    const int*   mask  = (const int*)d_in[3];
    const float* W1 = (const float*)d_in[4];
    const float* b1 = (const float*)d_in[5];
    const float* W2 = (const float*)d_in[6];
    const float* b2 = (const float*)d_in[7];
    const float* W3 = (const float*)d_in[8];
    const float* b3 = (const float*)d_in[9];

    float* out  = (float*)d_out;                 // [B, LQ, D]
    float* attn = out + (long)BB * LQ * DD;      // [B, LQ, LK]

    cudaFuncSetAttribute(proj_mma_kernel,
                         cudaFuncAttributeMaxDynamicSharedMemorySize, PM_SMEM);
    cudaFuncSetAttribute(score_mma_kernel,
                         cudaFuncAttributeMaxDynamicSharedMemorySize, SMEM_BYTES);
    cudaFuncSetAttribute(fused_softmax_av_kernel,
                         cudaFuncAttributeMaxDynamicSharedMemorySize, F_SMEM_BYTES);

    proj_mma_kernel<<<dim3(LQ / 16, BB, 3), 512, PM_SMEM>>>(query, key, W1, b1, W2);
    score_mma_kernel<<<SGRID, 512, SMEM_BYTES>>>(b2, W3, b3, attn);
    fused_softmax_av_kernel<<<dim3(LQ / 16, 2, BB), 256, F_SMEM_BYTES>>>(value, mask, out, attn);
}